// round 15
// baseline (speedup 1.0000x reference)
#include <cuda_runtime.h>
#include <cuda_bf16.h>
#include <cstdint>

// Problem dims
#define BB    4
#define TT    2048
#define DM    1024
#define DKV   512
#define CHUNK 128
#define NC    (TT / CHUNK)   // 16
#define MTOT  (BB * TT)      // 8192
#define NQKV  (3 * DKV)      // 1536

#define NSM_SLOTS 296        // 148 SMs x 2 CTAs (persistent grid)
#define NQT   768            // QKV tiles (64 m x 12 n)
#define NPT   64             // P tiles
#define NST   1024           // S tiles
#define NCONS (NPT + NST)    // 1088 consumer tiles

typedef __nv_bfloat16 bf16;

// ---------------------------------------------------------------------------
// Scratch
// ---------------------------------------------------------------------------
__device__ float g_S[(long)BB * NC * DKV * DKV];

__device__ bf16 g_xh[MTOT * DM];
__device__ bf16 g_xl[MTOT * DM];
__device__ bf16 g_Wh[NQKV * DM];
__device__ bf16 g_Wl[NQKV * DM];
__device__ bf16 g_Woh[DM * DKV];
__device__ bf16 g_Wol[DM * DKV];
__device__ bf16 g_QKVh[(long)MTOT * NQKV];
__device__ bf16 g_QKVl[(long)MTOT * NQKV];
__device__ bf16 g_Mh[(long)BB * NC * DKV * DKV];
__device__ bf16 g_Ml[(long)BB * NC * DKV * DKV];
__device__ bf16 g_Ph[BB * NC * CHUNK * CHUNK];
__device__ bf16 g_Pl[BB * NC * CHUNK * CHUNK];
__device__ bf16 g_Yh[MTOT * DKV];
__device__ bf16 g_Yl[MTOT * DKV];

__device__ int g_tdone[NQT];   // per-QKV-tile completion flags
__device__ int g_qctr;         // consumer work queue counter

// ---------------------------------------------------------------------------
// Helpers
// ---------------------------------------------------------------------------
__device__ __forceinline__ uint32_t smem_u32(const void* p) {
    uint32_t a;
    asm("{ .reg .u64 t; cvta.to.shared.u64 t, %1; cvt.u32.u64 %0, t; }" : "=r"(a) : "l"(p));
    return a;
}

#define CPASYNC16(s, g) \
    asm volatile("cp.async.cg.shared.global [%0], [%1], 16;" :: "r"(s), "l"(g))
#define CPCOMMIT() asm volatile("cp.async.commit_group;" ::: "memory")
#define CPWAIT1()  asm volatile("cp.async.wait_group 1;" ::: "memory")
#define CPWAIT0()  asm volatile("cp.async.wait_group 0;" ::: "memory")

#define LDSM4(r0, r1, r2, r3, a) \
    asm volatile("ldmatrix.sync.aligned.m8n8.x4.shared.b16 {%0,%1,%2,%3}, [%4];" \
                 : "=r"(r0), "=r"(r1), "=r"(r2), "=r"(r3) : "r"(a))
#define LDSM4T(r0, r1, r2, r3, a) \
    asm volatile("ldmatrix.sync.aligned.m8n8.x4.trans.shared.b16 {%0,%1,%2,%3}, [%4];" \
                 : "=r"(r0), "=r"(r1), "=r"(r2), "=r"(r3) : "r"(a))

#define MMA16816(d, a, b) \
    asm volatile("mma.sync.aligned.m16n8k16.row.col.f32.bf16.bf16.f32 " \
                 "{%0,%1,%2,%3},{%4,%5,%6,%7},{%8,%9},{%0,%1,%2,%3};" \
                 : "+f"((d)[0]), "+f"((d)[1]), "+f"((d)[2]), "+f"((d)[3]) \
                 : "r"((a)[0]), "r"((a)[1]), "r"((a)[2]), "r"((a)[3]), \
                   "r"((b)[0]), "r"((b)[1]))

#define MMA_TERMS_4x4(acc, a_h, a_l, b_h, b_l) do {                    \
    _Pragma("unroll")                                                  \
    for (int mt = 0; mt < 4; mt++)                                     \
        _Pragma("unroll")                                              \
        for (int nt = 0; nt < 4; nt++)                                 \
            MMA16816(acc[mt][nt], a_h[mt], b_h[nt]);                   \
    _Pragma("unroll")                                                  \
    for (int mt = 0; mt < 4; mt++)                                     \
        _Pragma("unroll")                                              \
        for (int nt = 0; nt < 4; nt++)                                 \
            MMA16816(acc[mt][nt], a_h[mt], b_l[nt]);                   \
    _Pragma("unroll")                                                  \
    for (int mt = 0; mt < 4; mt++)                                     \
        _Pragma("unroll")                                              \
        for (int nt = 0; nt < 4; nt++)                                 \
            MMA16816(acc[mt][nt], a_l[mt], b_h[nt]);                   \
} while (0)

#define MMA_TERMS_4x8(acc, a_h, a_l, b_h, b_l) do {                    \
    _Pragma("unroll")                                                  \
    for (int mt = 0; mt < 4; mt++)                                     \
        _Pragma("unroll")                                              \
        for (int nt = 0; nt < 8; nt++)                                 \
            MMA16816(acc[mt][nt], a_h[mt], b_h[nt]);                   \
    _Pragma("unroll")                                                  \
    for (int mt = 0; mt < 4; mt++)                                     \
        _Pragma("unroll")                                              \
        for (int nt = 0; nt < 8; nt++)                                 \
            MMA16816(acc[mt][nt], a_h[mt], b_l[nt]);                   \
    _Pragma("unroll")                                                  \
    for (int mt = 0; mt < 4; mt++)                                     \
        _Pragma("unroll")                                              \
        for (int nt = 0; nt < 8; nt++)                                 \
            MMA16816(acc[mt][nt], a_l[mt], b_h[nt]);                   \
} while (0)

__device__ __forceinline__ void split_hilo(float v, bf16& h, bf16& l) {
    h = __float2bfloat16(v);
    l = __float2bfloat16(v - __bfloat162float(h));
}

// Layout constants
#define NT_MROW 64
#define NT_MAT  (128 * NT_MROW)    // 8192
#define NT_STG  (4 * NT_MAT)       // 32768
#define NT_NSTG 3
#define NT_SMEM (NT_NSTG * NT_STG) // 98304

#define TN_ROW  272
#define TN_MAT  (32 * TN_ROW)      // 8704
#define TN_STG  (4 * TN_MAT)       // 34816

#define P_MROW  80
#define P_MAT   (128 * P_MROW)     // 10240
#define P_STG   (4 * P_MAT)        // 40960

__device__ __forceinline__ uint32_t swz64(int row, int c16) {
    return (uint32_t)(row * 64 + ((c16 ^ ((row >> 1) & 3)) << 4));
}

// ===========================================================================
// MEGA-KERNEL: QKV projection (producer) + P and S (consumers via flags+queue)
// 296 CTAs x 256 threads, 2 CTAs/SM guaranteed (smem 96KB, regs <=128).
// ===========================================================================
__global__ __launch_bounds__(256, 2)
void qsp_mma()
{
    extern __shared__ char smem[];
    __shared__ int s_qi;
    const uint32_t sb = smem_u32(smem);
    const int tid = threadIdx.x;
    const int L   = tid & 31;
    const int w   = tid >> 5;
    const int wm  = w >> 2;       // 0..1
    const int wn  = w & 3;        // 0..3

    // ------------------- Phase 1: QKV tiles (producer) ---------------------
    for (int t = blockIdx.x; t < NQT; t += NSM_SLOTS) {
        const int bm  = (t / 12) * 128;
        const int bnG = (t % 12) * 128;

        const int lrow = tid & 127;
        const int lc0  = tid >> 7;

        float acc[4][4][4];
        #pragma unroll
        for (int i = 0; i < 4; i++)
            #pragma unroll
            for (int j = 0; j < 4; j++) {
                acc[i][j][0] = 0.f; acc[i][j][1] = 0.f;
                acc[i][j][2] = 0.f; acc[i][j][3] = 0.f;
            }

        auto load_stage = [&](int stg, int k0) {
            uint32_t sbase = sb + (uint32_t)stg * NT_STG;
            long ga = (long)(bm + lrow) * DM + k0;
            long gb = (long)(bnG + lrow) * DM + k0;
            #pragma unroll
            for (int i2 = 0; i2 < 2; i2++) {
                int c16 = lc0 + i2 * 2;
                uint32_t dsw = sbase + swz64(lrow, c16);
                CPASYNC16(dsw + 0 * NT_MAT, g_xh + ga + c16 * 8);
                CPASYNC16(dsw + 1 * NT_MAT, g_xl + ga + c16 * 8);
                CPASYNC16(dsw + 2 * NT_MAT, g_Wh + gb + c16 * 8);
                CPASYNC16(dsw + 3 * NT_MAT, g_Wl + gb + c16 * 8);
            }
        };
        auto compute_stage = [&](int stg) {
            const uint32_t s0 = sb + (uint32_t)stg * NT_STG;
            #pragma unroll
            for (int kk = 0; kk < 2; kk++) {
                uint32_t a_h[4][4], a_l[4][4], b_h[4][2], b_l[4][2];
                const int arow = wm * 64 + (L & 7) + ((L >> 3) & 1) * 8;
                const int ac16 = kk * 2 + ((L >> 4) & 1);
                #pragma unroll
                for (int mt = 0; mt < 4; mt++) {
                    uint32_t ad = s0 + swz64(arow + mt * 16, ac16);
                    LDSM4(a_h[mt][0], a_h[mt][1], a_h[mt][2], a_h[mt][3], ad);
                    LDSM4(a_l[mt][0], a_l[mt][1], a_l[mt][2], a_l[mt][3], ad + NT_MAT);
                }
                const int brow = wn * 32 + (L & 7) + ((L >> 4) & 1) * 8;
                const int bc16 = kk * 2 + ((L >> 3) & 1);
                #pragma unroll
                for (int p = 0; p < 2; p++) {
                    uint32_t bd = s0 + 2 * NT_MAT + swz64(brow + p * 16, bc16);
                    uint32_t r0, r1, r2, r3;
                    LDSM4(r0, r1, r2, r3, bd);
                    b_h[2 * p][0] = r0; b_h[2 * p][1] = r1;
                    b_h[2 * p + 1][0] = r2; b_h[2 * p + 1][1] = r3;
                    LDSM4(r0, r1, r2, r3, bd + NT_MAT);
                    b_l[2 * p][0] = r0; b_l[2 * p][1] = r1;
                    b_l[2 * p + 1][0] = r2; b_l[2 * p + 1][1] = r3;
                }
                MMA_TERMS_4x4(acc, a_h, a_l, b_h, b_l);
            }
        };

        const int iters = DM >> 5;   // 32
        load_stage(0, 0);
        CPCOMMIT();
        load_stage(1, 32);
        CPCOMMIT();
        int ld_stg = 2, cp_stg = 0;
        for (int it = 0; it < iters; it++) {
            if (it + 2 < iters) CPWAIT1(); else CPWAIT0();
            __syncthreads();
            if (it + 2 < iters) {
                load_stage(ld_stg, (it + 2) * 32);
                CPCOMMIT();
                if (++ld_stg == NT_NSTG) ld_stg = 0;
            }
            compute_stage(cp_stg);
            if (++cp_stg == NT_NSTG) cp_stg = 0;
        }

        #pragma unroll
        for (int mt = 0; mt < 4; mt++)
            #pragma unroll
            for (int nt = 0; nt < 4; nt++) {
                int rr = bm + wm * 64 + mt * 16 + (L >> 2);
                int cc = bnG + wn * 32 + nt * 8 + (L & 3) * 2;
                __nv_bfloat162 h2, l2;
                split_hilo(acc[mt][nt][0], h2.x, l2.x);
                split_hilo(acc[mt][nt][1], h2.y, l2.y);
                *(__nv_bfloat162*)&g_QKVh[(long)rr * NQKV + cc] = h2;
                *(__nv_bfloat162*)&g_QKVl[(long)rr * NQKV + cc] = l2;
                split_hilo(acc[mt][nt][2], h2.x, l2.x);
                split_hilo(acc[mt][nt][3], h2.y, l2.y);
                *(__nv_bfloat162*)&g_QKVh[(long)(rr + 8) * NQKV + cc] = h2;
                *(__nv_bfloat162*)&g_QKVl[(long)(rr + 8) * NQKV + cc] = l2;
            }

        __threadfence();
        __syncthreads();
        if (tid == 0) atomicExch(&g_tdone[t], 1);
    }

    // ------------------- Phase 2: consumer queue (P then S) ----------------
    while (true) {
        if (tid == 0) s_qi = atomicAdd(&g_qctr, 1);
        __syncthreads();
        const int qi = s_qi;
        if (qi >= NCONS) break;

        if (qi < NPT) {
            // ---- P tile z = qi: strict_tril(Q_z K_z^T), K=512 ----
            const int z = qi;
            if (tid == 0) {
                #pragma unroll
                for (int f = 0; f < 8; f++)
                    while (((volatile int*)g_tdone)[z * 12 + f] == 0) { }
                __threadfence();
            }
            __syncthreads();

            const bf16* Ah = g_QKVh + (long)z * CHUNK * NQKV;          // Q
            const bf16* Al = g_QKVl + (long)z * CHUNK * NQKV;
            const bf16* Bh = g_QKVh + DKV + (long)z * CHUNK * NQKV;    // K
            const bf16* Bl = g_QKVl + DKV + (long)z * CHUNK * NQKV;
            bf16* CH = g_Ph + (long)z * CHUNK * CHUNK;
            bf16* CL = g_Pl + (long)z * CHUNK * CHUNK;

            const int lrow = tid & 127;
            const int lc0  = tid >> 7;

            float acc[4][4][4];
            #pragma unroll
            for (int i = 0; i < 4; i++)
                #pragma unroll
                for (int j = 0; j < 4; j++) {
                    acc[i][j][0] = 0.f; acc[i][j][1] = 0.f;
                    acc[i][j][2] = 0.f; acc[i][j][3] = 0.f;
                }

            auto load_stage = [&](int stg, int k0) {
                uint32_t sdst = sb + (uint32_t)stg * P_STG + (uint32_t)lrow * P_MROW;
                const bf16* aR = Ah + (long)lrow * NQKV + k0;
                const bf16* lR = Al + (long)lrow * NQKV + k0;
                const bf16* bR = Bh + (long)lrow * NQKV + k0;
                const bf16* mR = Bl + (long)lrow * NQKV + k0;
                #pragma unroll
                for (int i2 = 0; i2 < 2; i2++) {
                    int c16 = lc0 + i2 * 2;
                    CPASYNC16(sdst + 0 * P_MAT + c16 * 16, aR + c16 * 8);
                    CPASYNC16(sdst + 1 * P_MAT + c16 * 16, lR + c16 * 8);
                    CPASYNC16(sdst + 2 * P_MAT + c16 * 16, bR + c16 * 8);
                    CPASYNC16(sdst + 3 * P_MAT + c16 * 16, mR + c16 * 8);
                }
            };
            auto compute_stage = [&](int stg) {
                const uint32_t s0 = sb + (uint32_t)stg * P_STG;
                #pragma unroll
                for (int kk = 0; kk < 2; kk++) {
                    uint32_t a_h[4][4], a_l[4][4], b_h[4][2], b_l[4][2];
                    const int arow  = wm * 64 + (L & 7) + ((L >> 3) & 1) * 8;
                    const int acolB = kk * 32 + ((L >> 4) & 1) * 16;
                    #pragma unroll
                    for (int mt = 0; mt < 4; mt++) {
                        uint32_t ad = s0 + (uint32_t)(arow + mt * 16) * P_MROW + acolB;
                        LDSM4(a_h[mt][0], a_h[mt][1], a_h[mt][2], a_h[mt][3], ad);
                        LDSM4(a_l[mt][0], a_l[mt][1], a_l[mt][2], a_l[mt][3], ad + P_MAT);
                    }
                    const int brow  = wn * 32 + (L & 7) + ((L >> 4) & 1) * 8;
                    const int bcolB = kk * 32 + ((L >> 3) & 1) * 16;
                    #pragma unroll
                    for (int p = 0; p < 2; p++) {
                        uint32_t bd = s0 + 2 * P_MAT + (uint32_t)(brow + p * 16) * P_MROW + bcolB;
                        uint32_t r0, r1, r2, r3;
                        LDSM4(r0, r1, r2, r3, bd);
                        b_h[2 * p][0] = r0; b_h[2 * p][1] = r1;
                        b_h[2 * p + 1][0] = r2; b_h[2 * p + 1][1] = r3;
                        LDSM4(r0, r1, r2, r3, bd + P_MAT);
                        b_l[2 * p][0] = r0; b_l[2 * p][1] = r1;
                        b_l[2 * p + 1][0] = r2; b_l[2 * p + 1][1] = r3;
                    }
                    MMA_TERMS_4x4(acc, a_h, a_l, b_h, b_l);
                }
            };

            const int iters = DKV >> 5;   // 16
            load_stage(0, 0);
            CPCOMMIT();
            for (int it = 0; it < iters; it++) {
                if (it + 1 < iters) {
                    load_stage((it + 1) & 1, (it + 1) * 32);
                    CPCOMMIT();
                    CPWAIT1();
                } else {
                    CPWAIT0();
                }
                __syncthreads();
                compute_stage(it & 1);
                __syncthreads();
            }

            #pragma unroll
            for (int mt = 0; mt < 4; mt++)
                #pragma unroll
                for (int nt = 0; nt < 4; nt++) {
                    int rr = wm * 64 + mt * 16 + (L >> 2);
                    int cc = wn * 32 + nt * 8 + (L & 3) * 2;
                    float d0 = acc[mt][nt][0], d1 = acc[mt][nt][1];
                    float d2 = acc[mt][nt][2], d3 = acc[mt][nt][3];
                    if (cc     >= rr)     d0 = 0.0f;
                    if (cc + 1 >= rr)     d1 = 0.0f;
                    if (cc     >= rr + 8) d2 = 0.0f;
                    if (cc + 1 >= rr + 8) d3 = 0.0f;
                    __nv_bfloat162 h2, l2;
                    split_hilo(d0, h2.x, l2.x); split_hilo(d1, h2.y, l2.y);
                    *(__nv_bfloat162*)&CH[(long)rr * CHUNK + cc] = h2;
                    *(__nv_bfloat162*)&CL[(long)rr * CHUNK + cc] = l2;
                    split_hilo(d2, h2.x, l2.x); split_hilo(d3, h2.y, l2.y);
                    *(__nv_bfloat162*)&CH[(long)(rr + 8) * CHUNK + cc] = h2;
                    *(__nv_bfloat162*)&CL[(long)(rr + 8) * CHUNK + cc] = l2;
                }
        } else {
            // ---- S tile: S_z[bm,bn] = K_z^T V_z, K=128 ----
            const int s  = qi - NPT;
            const int z  = s >> 4;
            const int bm = ((s >> 2) & 3) * 128;
            const int bn = (s & 3) * 128;
            if (tid == 0) {
                while (((volatile int*)g_tdone)[z * 12 + 4 + (bm >> 7)] == 0) { }
                while (((volatile int*)g_tdone)[z * 12 + 8 + (bn >> 7)] == 0) { }
                __threadfence();
            }
            __syncthreads();

            const bf16* Ah = g_QKVh + DKV      + (long)z * CHUNK * NQKV;   // K
            const bf16* Al = g_QKVl + DKV      + (long)z * CHUNK * NQKV;
            const bf16* Bh = g_QKVh + 2 * DKV  + (long)z * CHUNK * NQKV;   // V
            const bf16* Bl = g_QKVl + 2 * DKV  + (long)z * CHUNK * NQKV;
            float* C = g_S + (long)z * DKV * DKV;

            float acc[4][4][4];
            #pragma unroll
            for (int i = 0; i < 4; i++)
                #pragma unroll
                for (int j = 0; j < 4; j++) {
                    acc[i][j][0] = 0.f; acc[i][j][1] = 0.f;
                    acc[i][j][2] = 0.f; acc[i][j][3] = 0.f;
                }

            auto load_stage = [&](int stg, int k0) {
                #pragma unroll
                for (int i = 0; i < 8; i++) {
                    int lin = tid + i * 256;
                    int mat = lin >> 9;
                    int rem2 = lin & 511;
                    int r   = rem2 >> 4;
                    int c16 = rem2 & 15;
                    const bf16* src = (mat == 0) ? Ah : (mat == 1) ? Al : (mat == 2) ? Bh : Bl;
                    int colb = (mat < 2) ? bm : bn;
                    src += (long)(k0 + r) * NQKV + colb + c16 * 8;
                    uint32_t dst = sb + (uint32_t)stg * TN_STG + mat * TN_MAT
                                 + (uint32_t)r * TN_ROW + c16 * 16;
                    CPASYNC16(dst, src);
                }
            };
            auto compute_stage = [&](int stg) {
                const uint32_t s0 = sb + (uint32_t)stg * TN_STG;
                #pragma unroll
                for (int kk = 0; kk < 2; kk++) {
                    uint32_t a_h[4][4], a_l[4][4], b_h[4][2], b_l[4][2];
                    const int akrow = kk * 16 + (L & 7) + ((L >> 4) & 1) * 8;
                    const int amcol = ((L >> 3) & 1) * 8;
                    #pragma unroll
                    for (int mt = 0; mt < 4; mt++) {
                        uint32_t ad = s0 + (uint32_t)akrow * TN_ROW
                                    + (uint32_t)(wm * 64 + mt * 16 + amcol) * 2;
                        LDSM4T(a_h[mt][0], a_h[mt][1], a_h[mt][2], a_h[mt][3], ad);
                        LDSM4T(a_l[mt][0], a_l[mt][1], a_l[mt][2], a_l[mt][3], ad + TN_MAT);
                    }
                    const int bkrow = kk * 16 + (L & 7) + ((L >> 3) & 1) * 8;
                    const int bncol = ((L >> 4) & 1) * 8;
                    #pragma unroll
                    for (int p = 0; p < 2; p++) {
                        uint32_t bd = s0 + 2 * TN_MAT + (uint32_t)bkrow * TN_ROW
                                    + (uint32_t)(wn * 32 + p * 16 + bncol) * 2;
                        uint32_t r0, r1, r2, r3;
                        LDSM4T(r0, r1, r2, r3, bd);
                        b_h[2 * p][0] = r0; b_h[2 * p][1] = r1;
                        b_h[2 * p + 1][0] = r2; b_h[2 * p + 1][1] = r3;
                        LDSM4T(r0, r1, r2, r3, bd + TN_MAT);
                        b_l[2 * p][0] = r0; b_l[2 * p][1] = r1;
                        b_l[2 * p + 1][0] = r2; b_l[2 * p + 1][1] = r3;
                    }
                    MMA_TERMS_4x4(acc, a_h, a_l, b_h, b_l);
                }
            };

            const int iters = CHUNK >> 5;   // 4
            load_stage(0, 0);
            CPCOMMIT();
            for (int it = 0; it < iters; it++) {
                if (it + 1 < iters) {
                    load_stage((it + 1) & 1, (it + 1) * 32);
                    CPCOMMIT();
                    CPWAIT1();
                } else {
                    CPWAIT0();
                }
                __syncthreads();
                compute_stage(it & 1);
                __syncthreads();
            }

            #pragma unroll
            for (int mt = 0; mt < 4; mt++)
                #pragma unroll
                for (int nt = 0; nt < 4; nt++) {
                    int rr = bm + wm * 64 + mt * 16 + (L >> 2);
                    int cc = bn + wn * 32 + nt * 8 + (L & 3) * 2;
                    *(float2*)&C[(long)rr * DKV + cc]       = make_float2(acc[mt][nt][0], acc[mt][nt][1]);
                    *(float2*)&C[(long)(rr + 8) * DKV + cc] = make_float2(acc[mt][nt][2], acc[mt][nt][3]);
                }
        }
        __syncthreads();   // protect smem + s_qi before next queue round
    }
}

// ===========================================================================
// y_mma: Y_c = P_c V_c + Q_c M_c   (unchanged from R14)
// ===========================================================================
#define YROW    80
#define Y_AMAT  (128 * YROW)
#define Y_BOFF  (2 * Y_AMAT)
#define Y_BMAT  (32 * TN_ROW)
#define Y_STG   (Y_BOFF + 2 * Y_BMAT)
#define Y_SMEM  (2 * Y_STG)
#define Y_ITERS 20

__global__ __launch_bounds__(256)
void y_mma()
{
    extern __shared__ char smem[];
    const uint32_t sb = smem_u32(smem);
    const int tid = threadIdx.x;
    const int L   = tid & 31;
    const int w   = tid >> 5;
    const int wm  = w >> 2;
    const int wn  = w & 3;

    const int bn = blockIdx.y * 128;
    const int z  = blockIdx.x;

    const bf16* Ph = g_Ph + (long)z * CHUNK * CHUNK;
    const bf16* Pl = g_Pl + (long)z * CHUNK * CHUNK;
    const bf16* Vh = g_QKVh + 2 * DKV + (long)z * CHUNK * NQKV;
    const bf16* Vl = g_QKVl + 2 * DKV + (long)z * CHUNK * NQKV;
    const bf16* Qh = g_QKVh + (long)z * CHUNK * NQKV;
    const bf16* Ql = g_QKVl + (long)z * CHUNK * NQKV;
    const bf16* Mh = g_Mh + (long)z * DKV * DKV;
    const bf16* Ml = g_Ml + (long)z * DKV * DKV;

    float acc[4][4][4];
    #pragma unroll
    for (int i = 0; i < 4; i++)
        #pragma unroll
        for (int j = 0; j < 4; j++) {
            acc[i][j][0] = 0.f; acc[i][j][1] = 0.f;
            acc[i][j][2] = 0.f; acc[i][j][3] = 0.f;
        }

    auto load_stage = [&](int stg, int it) {
        const int ph1 = (it < 4);
        const int k0  = ph1 ? it * 32 : (it - 4) * 32;
        const bf16* APh = ph1 ? Ph : Qh;
        const bf16* APl = ph1 ? Pl : Ql;
        const int   Alda = ph1 ? CHUNK : NQKV;
        const bf16* BPh = ph1 ? Vh : Mh;
        const bf16* BPl = ph1 ? Vl : Ml;
        const int   Bldb = ph1 ? NQKV : DKV;
        #pragma unroll
        for (int i = 0; i < 4; i++) {
            int lin = tid + i * 256;
            int mat = lin >> 9;
            int rem = lin & 511;
            int r   = rem >> 2;
            int c16 = rem & 3;
            const bf16* src = (mat ? APl : APh) + (long)r * Alda + k0 + c16 * 8;
            uint32_t dst = sb + (uint32_t)stg * Y_STG + mat * Y_AMAT
                         + (uint32_t)r * YROW + c16 * 16;
            CPASYNC16(dst, src);
        }
        #pragma unroll
        for (int i = 0; i < 4; i++) {
            int lin = tid + i * 256;
            int mat = lin >> 9;
            int rem = lin & 511;
            int r   = rem >> 4;
            int c16 = rem & 15;
            const bf16* src = (mat ? BPl : BPh) + (long)(k0 + r) * Bldb + bn + c16 * 8;
            uint32_t dst = sb + (uint32_t)stg * Y_STG + Y_BOFF + mat * Y_BMAT
                         + (uint32_t)r * TN_ROW + c16 * 16;
            CPASYNC16(dst, src);
        }
    };
    auto compute_stage = [&](int stg) {
        const uint32_t s0 = sb + (uint32_t)stg * Y_STG;
        #pragma unroll
        for (int kk = 0; kk < 2; kk++) {
            uint32_t a_h[4][4], a_l[4][4], b_h[4][2], b_l[4][2];
            const int arow  = wm * 64 + (L & 7) + ((L >> 3) & 1) * 8;
            const int acolB = kk * 32 + ((L >> 4) & 1) * 16;
            #pragma unroll
            for (int mt = 0; mt < 4; mt++) {
                uint32_t ad = s0 + (uint32_t)(arow + mt * 16) * YROW + acolB;
                LDSM4(a_h[mt][0], a_h[mt][1], a_h[mt][2], a_h[mt][3], ad);
                LDSM4(a_l[mt][0], a_l[mt][1], a_l[mt][2], a_l[mt][3], ad + Y_AMAT);
            }
            const int bkrow = kk * 16 + (L & 7) + ((L >> 3) & 1) * 8;
            const int bncol = ((L >> 4) & 1) * 8;
            #pragma unroll
            for (int p = 0; p < 2; p++) {
                uint32_t bd = s0 + Y_BOFF + (uint32_t)bkrow * TN_ROW
                            + (uint32_t)(wn * 32 + p * 16 + bncol) * 2;
                uint32_t r0, r1, r2, r3;
                LDSM4T(r0, r1, r2, r3, bd);
                b_h[2 * p][0] = r0; b_h[2 * p][1] = r1;
                b_h[2 * p + 1][0] = r2; b_h[2 * p + 1][1] = r3;
                LDSM4T(r0, r1, r2, r3, bd + Y_BMAT);
                b_l[2 * p][0] = r0; b_l[2 * p][1] = r1;
                b_l[2 * p + 1][0] = r2; b_l[2 * p + 1][1] = r3;
            }
            MMA_TERMS_4x4(acc, a_h, a_l, b_h, b_l);
        }
    };

    load_stage(0, 0);
    CPCOMMIT();
    for (int it = 0; it < Y_ITERS; it++) {
        if (it + 1 < Y_ITERS) {
            load_stage((it + 1) & 1, it + 1);
            CPCOMMIT();
            CPWAIT1();
        } else {
            CPWAIT0();
        }
        __syncthreads();
        compute_stage(it & 1);
        __syncthreads();
    }

    bf16* YH = g_Yh + (long)z * CHUNK * DKV;
    bf16* YL = g_Yl + (long)z * CHUNK * DKV;
    #pragma unroll
    for (int mt = 0; mt < 4; mt++)
        #pragma unroll
        for (int nt = 0; nt < 4; nt++) {
            int rr = wm * 64 + mt * 16 + (L >> 2);
            int cc = bn + wn * 32 + nt * 8 + (L & 3) * 2;
            __nv_bfloat162 h2, l2;
            split_hilo(acc[mt][nt][0], h2.x, l2.x);
            split_hilo(acc[mt][nt][1], h2.y, l2.y);
            *(__nv_bfloat162*)&YH[(long)rr * DKV + cc] = h2;
            *(__nv_bfloat162*)&YL[(long)rr * DKV + cc] = l2;
            split_hilo(acc[mt][nt][2], h2.x, l2.x);
            split_hilo(acc[mt][nt][3], h2.y, l2.y);
            *(__nv_bfloat162*)&YH[(long)(rr + 8) * DKV + cc] = h2;
            *(__nv_bfloat162*)&YL[(long)(rr + 8) * DKV + cc] = l2;
        }
}

// ===========================================================================
// Wo GEMM: out = Y @ Wo^T — persistent 128-thread NT kernel (R14 body)
// ===========================================================================
__global__ __launch_bounds__(128, 2)
void wo_mma(float* __restrict__ out)
{
    extern __shared__ char smem[];
    const uint32_t sb = smem_u32(smem);
    const int tid = threadIdx.x;
    const int L   = tid & 31;
    const int w   = tid >> 5;
    const int wm  = w >> 1;
    const int wn  = w & 1;
    const int iters = DKV >> 5;   // 16
    const int total = (MTOT / 128) * (DM / 128);   // 512

    for (int t = blockIdx.x; t < total; t += gridDim.x) {
        const int bm = (t / (DM / 128)) * 128;
        const int bn = (t % (DM / 128)) * 128;

        float acc[4][8][4];
        #pragma unroll
        for (int i = 0; i < 4; i++)
            #pragma unroll
            for (int j = 0; j < 8; j++) {
                acc[i][j][0] = 0.f; acc[i][j][1] = 0.f;
                acc[i][j][2] = 0.f; acc[i][j][3] = 0.f;
            }

        auto load_stage = [&](int stg, int k0) {
            uint32_t sbase = sb + (uint32_t)stg * NT_STG;
            const int lrow = tid;
            long ga = (long)(bm + lrow) * DKV + k0;
            long gb = (long)(bn + lrow) * DKV + k0;
            #pragma unroll
            for (int c16 = 0; c16 < 4; c16++) {
                uint32_t dsw = sbase + swz64(lrow, c16);
                CPASYNC16(dsw + 0 * NT_MAT, g_Yh + ga + c16 * 8);
                CPASYNC16(dsw + 1 * NT_MAT, g_Yl + ga + c16 * 8);
                CPASYNC16(dsw + 2 * NT_MAT, g_Woh + gb + c16 * 8);
                CPASYNC16(dsw + 3 * NT_MAT, g_Wol + gb + c16 * 8);
            }
        };
        auto compute_stage = [&](int stg) {
            const uint32_t s0 = sb + (uint32_t)stg * NT_STG;
            #pragma unroll
            for (int kk = 0; kk < 2; kk++) {
                uint32_t a_h[4][4], a_l[4][4], b_h[8][2], b_l[8][2];
                const int arow = wm * 64 + (L & 7) + ((L >> 3) & 1) * 8;
                const int ac16 = kk * 2 + ((L >> 4) & 1);
                #pragma unroll
                for (int mt = 0; mt < 4; mt++) {
                    uint32_t ad = s0 + swz64(arow + mt * 16, ac16);
                    LDSM4(a_h[mt][0], a_h[mt][1], a_h[mt][2], a_h[mt][3], ad);
                    LDSM4(a_l[mt][0], a_l[mt][1], a_l[mt][2], a_l[mt][3], ad + NT_MAT);
                }
                const int brow = wn * 64 + (L & 7) + ((L >> 4) & 1) * 8;
                const int bc16 = kk * 2 + ((L >> 3) & 1);
                #pragma unroll
                for (int p = 0; p < 4; p++) {
                    uint32_t bd = s0 + 2 * NT_MAT + swz64(brow + p * 16, bc16);
                    uint32_t r0, r1, r2, r3;
                    LDSM4(r0, r1, r2, r3, bd);
                    b_h[2 * p][0] = r0; b_h[2 * p][1] = r1;
                    b_h[2 * p + 1][0] = r2; b_h[2 * p + 1][1] = r3;
                    LDSM4(r0, r1, r2, r3, bd + NT_MAT);
                    b_l[2 * p][0] = r0; b_l[2 * p][1] = r1;
                    b_l[2 * p + 1][0] = r2; b_l[2 * p + 1][1] = r3;
                }
                MMA_TERMS_4x8(acc, a_h, a_l, b_h, b_l);
            }
        };

        load_stage(0, 0);
        CPCOMMIT();
        load_stage(1, 32);
        CPCOMMIT();
        int ld_stg = 2, cp_stg = 0;
        for (int it = 0; it < iters; it++) {
            if (it + 2 < iters) CPWAIT1(); else CPWAIT0();
            __syncthreads();
            if (it + 2 < iters) {
                load_stage(ld_stg, (it + 2) * 32);
                CPCOMMIT();
                if (++ld_stg == NT_NSTG) ld_stg = 0;
            }
            compute_stage(cp_stg);
            if (++cp_stg == NT_NSTG) cp_stg = 0;
        }

        #pragma unroll
        for (int mt = 0; mt < 4; mt++)
            #pragma unroll
            for (int nt = 0; nt < 8; nt++) {
                int rr = bm + wm * 64 + mt * 16 + (L >> 2);
                int cc = bn + wn * 64 + nt * 8 + (L & 3) * 2;
                *(float2*)&out[(long)rr * DM + cc]       = make_float2(acc[mt][nt][0], acc[mt][nt][1]);
                *(float2*)&out[(long)(rr + 8) * DM + cc] = make_float2(acc[mt][nt][2], acc[mt][nt][3]);
            }
        __syncthreads();
    }
}

// ---------------------------------------------------------------------------
// Exclusive prefix (MLP-16) — unchanged
// ---------------------------------------------------------------------------
__global__ __launch_bounds__(256)
void prefix_kernel()
{
    long idx = (long)blockIdx.x * blockDim.x + threadIdx.x;
    int  b   = (int)(idx / ((long)DKV * DKV));
    long ij  = idx % ((long)DKV * DKV);
    long base = (long)b * NC * DKV * DKV + ij;

    float s[NC];
    #pragma unroll
    for (int c = 0; c < NC; c++)
        s[c] = g_S[base + (long)c * DKV * DKV];

    float acc = 0.0f;
    #pragma unroll
    for (int c = 0; c < NC; c++) {
        bf16 hb, lb;
        split_hilo(acc, hb, lb);
        long off = base + (long)c * DKV * DKV;
        g_Mh[off] = hb;
        g_Ml[off] = lb;
        acc += s[c];
    }
}

// ---------------------------------------------------------------------------
// Input conversions (x also zeroes flags/queue; w4 covers Wq,Wk,Wv,Wo)
// ---------------------------------------------------------------------------
#define NW  ((long)DKV * DM)         // 524288

__global__ __launch_bounds__(256)
void cvt_x(const float* __restrict__ s)
{
    long i = (long)blockIdx.x * 256 + threadIdx.x;
    if (i < NQT) g_tdone[(int)i] = 0;
    if (i == NQT) g_qctr = 0;
    bf16 hb, lb;
    split_hilo(s[i], hb, lb);
    g_xh[i] = hb;
    g_xl[i] = lb;
}

__global__ __launch_bounds__(256)
void cvt_w4(const float* __restrict__ wq, const float* __restrict__ wk,
            const float* __restrict__ wv, const float* __restrict__ wo)
{
    long i = (long)blockIdx.x * 256 + threadIdx.x;   // over 4*NW
    const float* s;
    long j;
    bf16 *h, *l;
    if (i < NW)            { s = wq; j = i;          h = g_Wh;          l = g_Wl; }
    else if (i < 2 * NW)   { s = wk; j = i - NW;     h = g_Wh + NW;     l = g_Wl + NW; }
    else if (i < 3 * NW)   { s = wv; j = i - 2 * NW; h = g_Wh + 2 * NW; l = g_Wl + 2 * NW; }
    else                   { s = wo; j = i - 3 * NW; h = g_Woh;         l = g_Wol; }
    bf16 hb, lb;
    split_hilo(s[j], hb, lb);
    h[j] = hb;
    l[j] = lb;
}

// ---------------------------------------------------------------------------
// Launch
// ---------------------------------------------------------------------------
extern "C" void kernel_launch(void* const* d_in, const int* in_sizes, int n_in,
                              void* d_out, int out_size)
{
    const float* x  = (const float*)d_in[0];
    const float* Wq = (const float*)d_in[1];
    const float* Wk = (const float*)d_in[2];
    const float* Wv = (const float*)d_in[3];
    const float* Wo = (const float*)d_in[4];
    float* out = (float*)d_out;

    cudaFuncSetAttribute(qsp_mma, cudaFuncAttributeMaxDynamicSharedMemorySize, NT_SMEM);
    cudaFuncSetAttribute(y_mma,   cudaFuncAttributeMaxDynamicSharedMemorySize, Y_SMEM);
    cudaFuncSetAttribute(wo_mma,  cudaFuncAttributeMaxDynamicSharedMemorySize, NT_SMEM);

    // 0) conversions (cvt_x also resets flags + queue counter)
    {
        long nx = (long)MTOT * DM;
        cvt_x<<<(int)(nx / 256), 256>>>(x);
        cvt_w4<<<(int)(4 * NW / 256), 256>>>(Wq, Wk, Wv, Wo);
    }

    // 1) fused QKV + P + S (producer/consumer mega-kernel)
    qsp_mma<<<NSM_SLOTS, 256, NT_SMEM>>>();

    // 2) exclusive prefix -> M hi/lo
    {
        long n = (long)BB * DKV * DKV;
        prefix_kernel<<<(int)(n / 256), 256>>>();
    }

    // 3) Y_c = P_c V_c + Q_c M_c
    {
        dim3 grid(BB * NC, DKV / 128, 1);
        y_mma<<<grid, 256, Y_SMEM>>>();
    }

    // 4) out = Y @ Wo^T
    wo_mma<<<NSM_SLOTS, 128, NT_SMEM>>>(out);
}

// round 16
// speedup vs baseline: 1.0584x; 1.0584x over previous
#include <cuda_runtime.h>
#include <cuda_bf16.h>
#include <cstdint>

// Problem dims
#define BB    4
#define TT    2048
#define DM    1024
#define DKV   512
#define CHUNK 128
#define NC    (TT / CHUNK)   // 16
#define MTOT  (BB * TT)      // 8192
#define NQKV  (3 * DKV)      // 1536

#define NSM_SLOTS 296        // 148 SMs x 2 CTAs (persistent grid)

typedef __nv_bfloat16 bf16;

// ---------------------------------------------------------------------------
// Scratch
// ---------------------------------------------------------------------------
__device__ float g_S[(long)BB * NC * DKV * DKV];      // chunk states (fp32)

__device__ bf16 g_xh[MTOT * DM];
__device__ bf16 g_xl[MTOT * DM];
__device__ bf16 g_Wh[NQKV * DM];     // Wq|Wk|Wv stacked [1536,1024]
__device__ bf16 g_Wl[NQKV * DM];
__device__ bf16 g_Woh[DM * DKV];
__device__ bf16 g_Wol[DM * DKV];
__device__ bf16 g_QKVh[(long)MTOT * NQKV];   // Q|K|V cols, ld=1536
__device__ bf16 g_QKVl[(long)MTOT * NQKV];
__device__ bf16 g_Mh[(long)BB * NC * DKV * DKV];   // exclusive-prefix state
__device__ bf16 g_Ml[(long)BB * NC * DKV * DKV];
__device__ bf16 g_Ph[BB * NC * CHUNK * CHUNK];
__device__ bf16 g_Pl[BB * NC * CHUNK * CHUNK];
__device__ bf16 g_Yh[MTOT * DKV];
__device__ bf16 g_Yl[MTOT * DKV];

// ---------------------------------------------------------------------------
// Helpers
// ---------------------------------------------------------------------------
__device__ __forceinline__ uint32_t smem_u32(const void* p) {
    uint32_t a;
    asm("{ .reg .u64 t; cvta.to.shared.u64 t, %1; cvt.u32.u64 %0, t; }" : "=r"(a) : "l"(p));
    return a;
}

#define CPASYNC16(s, g) \
    asm volatile("cp.async.cg.shared.global [%0], [%1], 16;" :: "r"(s), "l"(g))
#define CPCOMMIT() asm volatile("cp.async.commit_group;" ::: "memory")
#define CPWAIT1()  asm volatile("cp.async.wait_group 1;" ::: "memory")
#define CPWAIT0()  asm volatile("cp.async.wait_group 0;" ::: "memory")

#define LDSM4(r0, r1, r2, r3, a) \
    asm volatile("ldmatrix.sync.aligned.m8n8.x4.shared.b16 {%0,%1,%2,%3}, [%4];" \
                 : "=r"(r0), "=r"(r1), "=r"(r2), "=r"(r3) : "r"(a))
#define LDSM4T(r0, r1, r2, r3, a) \
    asm volatile("ldmatrix.sync.aligned.m8n8.x4.trans.shared.b16 {%0,%1,%2,%3}, [%4];" \
                 : "=r"(r0), "=r"(r1), "=r"(r2), "=r"(r3) : "r"(a))

#define MMA16816(d, a, b) \
    asm volatile("mma.sync.aligned.m16n8k16.row.col.f32.bf16.bf16.f32 " \
                 "{%0,%1,%2,%3},{%4,%5,%6,%7},{%8,%9},{%0,%1,%2,%3};" \
                 : "+f"((d)[0]), "+f"((d)[1]), "+f"((d)[2]), "+f"((d)[3]) \
                 : "r"((a)[0]), "r"((a)[1]), "r"((a)[2]), "r"((a)[3]), \
                   "r"((b)[0]), "r"((b)[1]))

#define MMA_TERMS_4x4(acc, a_h, a_l, b_h, b_l) do {                    \
    _Pragma("unroll")                                                  \
    for (int mt = 0; mt < 4; mt++)                                     \
        _Pragma("unroll")                                              \
        for (int nt = 0; nt < 4; nt++)                                 \
            MMA16816(acc[mt][nt], a_h[mt], b_h[nt]);                   \
    _Pragma("unroll")                                                  \
    for (int mt = 0; mt < 4; mt++)                                     \
        _Pragma("unroll")                                              \
        for (int nt = 0; nt < 4; nt++)                                 \
            MMA16816(acc[mt][nt], a_h[mt], b_l[nt]);                   \
    _Pragma("unroll")                                                  \
    for (int mt = 0; mt < 4; mt++)                                     \
        _Pragma("unroll")                                              \
        for (int nt = 0; nt < 4; nt++)                                 \
            MMA16816(acc[mt][nt], a_l[mt], b_h[nt]);                   \
} while (0)

#define MMA_TERMS_4x8(acc, a_h, a_l, b_h, b_l) do {                    \
    _Pragma("unroll")                                                  \
    for (int mt = 0; mt < 4; mt++)                                     \
        _Pragma("unroll")                                              \
        for (int nt = 0; nt < 8; nt++)                                 \
            MMA16816(acc[mt][nt], a_h[mt], b_h[nt]);                   \
    _Pragma("unroll")                                                  \
    for (int mt = 0; mt < 4; mt++)                                     \
        _Pragma("unroll")                                              \
        for (int nt = 0; nt < 8; nt++)                                 \
            MMA16816(acc[mt][nt], a_h[mt], b_l[nt]);                   \
    _Pragma("unroll")                                                  \
    for (int mt = 0; mt < 4; mt++)                                     \
        _Pragma("unroll")                                              \
        for (int nt = 0; nt < 8; nt++)                                 \
            MMA16816(acc[mt][nt], a_l[mt], b_h[nt]);                   \
} while (0)

__device__ __forceinline__ void split_hilo(float v, bf16& h, bf16& l) {
    h = __float2bfloat16(v);
    l = __float2bfloat16(v - __bfloat162float(h));
}

// ===========================================================================
// Kernel 1: NT GEMM — bf16x3, PERSISTENT. CTA 128x128, 4 warps, 64x64 warp
// tile, swizzled 64B rows, 3 stages, one barrier/iter.  (QKV, Wo)
// ===========================================================================
#define NT_MROW 64
#define NT_MAT  (128 * NT_MROW)    // 8192
#define NT_STG  (4 * NT_MAT)       // 32768
#define NT_NSTG 3
#define NT_SMEM (NT_NSTG * NT_STG) // 98304

__device__ __forceinline__ uint32_t swz64(int row, int c16) {
    return (uint32_t)(row * 64 + ((c16 ^ ((row >> 1) & 3)) << 4));
}

__global__ __launch_bounds__(128, 2)
void gemm_mma_nt(const bf16* __restrict__ Ah_, const bf16* __restrict__ Al_,
                 const bf16* __restrict__ Bh_, const bf16* __restrict__ Bl_,
                 float* Cf, bf16* Ch, bf16* Cl,
                 int K, int lda, int ldb, int ldc,
                 int outmode, int nTm, int nTn)
{
    extern __shared__ char smem[];
    const uint32_t sb = smem_u32(smem);
    const int tid = threadIdx.x;
    const int L   = tid & 31;
    const int w   = tid >> 5;
    const int wm  = w >> 1;
    const int wn  = w & 1;
    const int iters = K >> 5;
    const int total = nTm * nTn;

    for (int t = blockIdx.x; t < total; t += gridDim.x) {
        const int bm  = (t / nTn) * 128;
        const int bn  = (t % nTn) * 128;

        float acc[4][8][4];
        #pragma unroll
        for (int i = 0; i < 4; i++)
            #pragma unroll
            for (int j = 0; j < 8; j++) {
                acc[i][j][0] = 0.f; acc[i][j][1] = 0.f;
                acc[i][j][2] = 0.f; acc[i][j][3] = 0.f;
            }

        auto load_stage = [&](int stg, int k0) {
            uint32_t sbase = sb + (uint32_t)stg * NT_STG;
            const int lrow = tid;
            long ga = (long)(bm + lrow) * lda + k0;
            long gb = (long)(bn + lrow) * ldb + k0;
            #pragma unroll
            for (int c16 = 0; c16 < 4; c16++) {
                uint32_t dsw = sbase + swz64(lrow, c16);
                CPASYNC16(dsw + 0 * NT_MAT, Ah_ + ga + c16 * 8);
                CPASYNC16(dsw + 1 * NT_MAT, Al_ + ga + c16 * 8);
                CPASYNC16(dsw + 2 * NT_MAT, Bh_ + gb + c16 * 8);
                CPASYNC16(dsw + 3 * NT_MAT, Bl_ + gb + c16 * 8);
            }
        };
        auto compute_stage = [&](int stg) {
            const uint32_t s0 = sb + (uint32_t)stg * NT_STG;
            #pragma unroll
            for (int kk = 0; kk < 2; kk++) {
                uint32_t a_h[4][4], a_l[4][4], b_h[8][2], b_l[8][2];
                const int arow = wm * 64 + (L & 7) + ((L >> 3) & 1) * 8;
                const int ac16 = kk * 2 + ((L >> 4) & 1);
                #pragma unroll
                for (int mt = 0; mt < 4; mt++) {
                    uint32_t ad = s0 + swz64(arow + mt * 16, ac16);
                    LDSM4(a_h[mt][0], a_h[mt][1], a_h[mt][2], a_h[mt][3], ad);
                    LDSM4(a_l[mt][0], a_l[mt][1], a_l[mt][2], a_l[mt][3], ad + NT_MAT);
                }
                const int brow = wn * 64 + (L & 7) + ((L >> 4) & 1) * 8;
                const int bc16 = kk * 2 + ((L >> 3) & 1);
                #pragma unroll
                for (int p = 0; p < 4; p++) {
                    uint32_t bd = s0 + 2 * NT_MAT + swz64(brow + p * 16, bc16);
                    uint32_t r0, r1, r2, r3;
                    LDSM4(r0, r1, r2, r3, bd);
                    b_h[2 * p][0] = r0; b_h[2 * p][1] = r1;
                    b_h[2 * p + 1][0] = r2; b_h[2 * p + 1][1] = r3;
                    LDSM4(r0, r1, r2, r3, bd + NT_MAT);
                    b_l[2 * p][0] = r0; b_l[2 * p][1] = r1;
                    b_l[2 * p + 1][0] = r2; b_l[2 * p + 1][1] = r3;
                }
                MMA_TERMS_4x8(acc, a_h, a_l, b_h, b_l);
            }
        };

        load_stage(0, 0);
        CPCOMMIT();
        load_stage(1, 32);
        CPCOMMIT();
        int ld_stg = 2, cp_stg = 0;
        for (int it = 0; it < iters; it++) {
            if (it + 2 < iters) CPWAIT1(); else CPWAIT0();
            __syncthreads();
            if (it + 2 < iters) {
                load_stage(ld_stg, (it + 2) * 32);
                CPCOMMIT();
                if (++ld_stg == NT_NSTG) ld_stg = 0;
            }
            compute_stage(cp_stg);
            if (++cp_stg == NT_NSTG) cp_stg = 0;
        }

        #pragma unroll
        for (int mt = 0; mt < 4; mt++) {
            #pragma unroll
            for (int nt = 0; nt < 8; nt++) {
                int rr = bm + wm * 64 + mt * 16 + (L >> 2);
                int cc = bn + wn * 64 + nt * 8 + (L & 3) * 2;
                float d0 = acc[mt][nt][0], d1 = acc[mt][nt][1];
                float d2 = acc[mt][nt][2], d3 = acc[mt][nt][3];
                if (outmode == 0) {
                    *(float2*)&Cf[(long)rr * ldc + cc]       = make_float2(d0, d1);
                    *(float2*)&Cf[(long)(rr + 8) * ldc + cc] = make_float2(d2, d3);
                } else {
                    __nv_bfloat162 h2, l2;
                    split_hilo(d0, h2.x, l2.x); split_hilo(d1, h2.y, l2.y);
                    *(__nv_bfloat162*)&Ch[(long)rr * ldc + cc] = h2;
                    *(__nv_bfloat162*)&Cl[(long)rr * ldc + cc] = l2;
                    split_hilo(d2, h2.x, l2.x); split_hilo(d3, h2.y, l2.y);
                    *(__nv_bfloat162*)&Ch[(long)(rr + 8) * ldc + cc] = h2;
                    *(__nv_bfloat162*)&Cl[(long)(rr + 8) * ldc + cc] = l2;
                }
            }
        }
        __syncthreads();
    }
}

// ===========================================================================
// Kernel 2: fused S+P persistent kernel (256 threads).
//  - CTAs 0..63:   P_z = strict_tril(Q_z K_z^T), 128x128, K=512 (NT, 80B pitch)
//  - CTAs 64..295: S tiles (z, bm, bn) of S_c = K_c^T V_c (TN, 272B pitch)
// ===========================================================================
#define TN_ROW  272
#define TN_MAT  (32 * TN_ROW)     // 8704
#define TN_STG  (4 * TN_MAT)      // 34816
#define TN_TM   (DKV / 128)       // 4
#define TN_TN   (DKV / 128)       // 4
#define TN_TOTAL (BB * NC * TN_TM * TN_TN)   // 1024

#define P_MROW  80
#define P_MAT   (128 * P_MROW)    // 10240
#define P_STG   (4 * P_MAT)       // 40960
#define SP_SMEM (2 * P_STG)       // 81920 (>= 2*TN_STG)

__global__ __launch_bounds__(256, 2)
void sp_mma()
{
    extern __shared__ char smem[];
    const uint32_t sb = smem_u32(smem);
    const int tid = threadIdx.x;
    const int L   = tid & 31;
    const int w   = tid >> 5;
    const int wm  = w >> 2;       // 0..1
    const int wn  = w & 3;        // 0..3
    const int bid = blockIdx.x;

    if (bid < BB * NC) {
        // ---------------- P path: one z-tile per CTA, NT, K=512 -----------
        const int z = bid;
        const bf16* Ah = g_QKVh + (long)z * CHUNK * NQKV;          // Q
        const bf16* Al = g_QKVl + (long)z * CHUNK * NQKV;
        const bf16* Bh = g_QKVh + DKV + (long)z * CHUNK * NQKV;    // K
        const bf16* Bl = g_QKVl + DKV + (long)z * CHUNK * NQKV;
        bf16* CH = g_Ph + (long)z * CHUNK * CHUNK;
        bf16* CL = g_Pl + (long)z * CHUNK * CHUNK;

        const int lrow = tid & 127;
        const int lc0  = tid >> 7;

        float acc[4][4][4];
        #pragma unroll
        for (int i = 0; i < 4; i++)
            #pragma unroll
            for (int j = 0; j < 4; j++) {
                acc[i][j][0] = 0.f; acc[i][j][1] = 0.f;
                acc[i][j][2] = 0.f; acc[i][j][3] = 0.f;
            }

        auto load_stage = [&](int stg, int k0) {
            uint32_t sdst = sb + (uint32_t)stg * P_STG + (uint32_t)lrow * P_MROW;
            const bf16* aR = Ah + (long)lrow * NQKV + k0;
            const bf16* lR = Al + (long)lrow * NQKV + k0;
            const bf16* bR = Bh + (long)lrow * NQKV + k0;
            const bf16* mR = Bl + (long)lrow * NQKV + k0;
            #pragma unroll
            for (int i2 = 0; i2 < 2; i2++) {
                int c16 = lc0 + i2 * 2;
                CPASYNC16(sdst + 0 * P_MAT + c16 * 16, aR + c16 * 8);
                CPASYNC16(sdst + 1 * P_MAT + c16 * 16, lR + c16 * 8);
                CPASYNC16(sdst + 2 * P_MAT + c16 * 16, bR + c16 * 8);
                CPASYNC16(sdst + 3 * P_MAT + c16 * 16, mR + c16 * 8);
            }
        };
        auto compute_stage = [&](int stg) {
            const uint32_t s0 = sb + (uint32_t)stg * P_STG;
            #pragma unroll
            for (int kk = 0; kk < 2; kk++) {
                uint32_t a_h[4][4], a_l[4][4], b_h[4][2], b_l[4][2];
                const int arow  = wm * 64 + (L & 7) + ((L >> 3) & 1) * 8;
                const int acolB = kk * 32 + ((L >> 4) & 1) * 16;
                #pragma unroll
                for (int mt = 0; mt < 4; mt++) {
                    uint32_t ad = s0 + (uint32_t)(arow + mt * 16) * P_MROW + acolB;
                    LDSM4(a_h[mt][0], a_h[mt][1], a_h[mt][2], a_h[mt][3], ad);
                    LDSM4(a_l[mt][0], a_l[mt][1], a_l[mt][2], a_l[mt][3], ad + P_MAT);
                }
                const int brow  = wn * 32 + (L & 7) + ((L >> 4) & 1) * 8;
                const int bcolB = kk * 32 + ((L >> 3) & 1) * 16;
                #pragma unroll
                for (int p = 0; p < 2; p++) {
                    uint32_t bd = s0 + 2 * P_MAT + (uint32_t)(brow + p * 16) * P_MROW + bcolB;
                    uint32_t r0, r1, r2, r3;
                    LDSM4(r0, r1, r2, r3, bd);
                    b_h[2 * p][0] = r0; b_h[2 * p][1] = r1;
                    b_h[2 * p + 1][0] = r2; b_h[2 * p + 1][1] = r3;
                    LDSM4(r0, r1, r2, r3, bd + P_MAT);
                    b_l[2 * p][0] = r0; b_l[2 * p][1] = r1;
                    b_l[2 * p + 1][0] = r2; b_l[2 * p + 1][1] = r3;
                }
                MMA_TERMS_4x4(acc, a_h, a_l, b_h, b_l);
            }
        };

        const int iters = DKV >> 5;   // 16
        load_stage(0, 0);
        CPCOMMIT();
        for (int it = 0; it < iters; it++) {
            if (it + 1 < iters) {
                load_stage((it + 1) & 1, (it + 1) * 32);
                CPCOMMIT();
                CPWAIT1();
            } else {
                CPWAIT0();
            }
            __syncthreads();
            compute_stage(it & 1);
            __syncthreads();
        }

        #pragma unroll
        for (int mt = 0; mt < 4; mt++)
            #pragma unroll
            for (int nt = 0; nt < 4; nt++) {
                int rr = wm * 64 + mt * 16 + (L >> 2);
                int cc = wn * 32 + nt * 8 + (L & 3) * 2;
                float d0 = acc[mt][nt][0], d1 = acc[mt][nt][1];
                float d2 = acc[mt][nt][2], d3 = acc[mt][nt][3];
                if (cc     >= rr)     d0 = 0.0f;
                if (cc + 1 >= rr)     d1 = 0.0f;
                if (cc     >= rr + 8) d2 = 0.0f;
                if (cc + 1 >= rr + 8) d3 = 0.0f;
                __nv_bfloat162 h2, l2;
                split_hilo(d0, h2.x, l2.x); split_hilo(d1, h2.y, l2.y);
                *(__nv_bfloat162*)&CH[(long)rr * CHUNK + cc] = h2;
                *(__nv_bfloat162*)&CL[(long)rr * CHUNK + cc] = l2;
                split_hilo(d2, h2.x, l2.x); split_hilo(d3, h2.y, l2.y);
                *(__nv_bfloat162*)&CH[(long)(rr + 8) * CHUNK + cc] = h2;
                *(__nv_bfloat162*)&CL[(long)(rr + 8) * CHUNK + cc] = l2;
            }
        return;
    }

    // ---------------- S path: strided tiles over 232 CTAs ------------------
    for (int t = bid - BB * NC; t < TN_TOTAL; t += (NSM_SLOTS - BB * NC)) {
        const int z   = t / (TN_TM * TN_TN);
        const int rem = t % (TN_TM * TN_TN);
        const int bm  = (rem / TN_TN) * 128;
        const int bn  = (rem % TN_TN) * 128;
        const bf16* Ah = g_QKVh + DKV      + (long)z * CHUNK * NQKV;   // K
        const bf16* Al = g_QKVl + DKV      + (long)z * CHUNK * NQKV;
        const bf16* Bh = g_QKVh + 2 * DKV  + (long)z * CHUNK * NQKV;   // V
        const bf16* Bl = g_QKVl + 2 * DKV  + (long)z * CHUNK * NQKV;
        float* C = g_S + (long)z * DKV * DKV;

        float acc[4][4][4];
        #pragma unroll
        for (int i = 0; i < 4; i++)
            #pragma unroll
            for (int j = 0; j < 4; j++) {
                acc[i][j][0] = 0.f; acc[i][j][1] = 0.f;
                acc[i][j][2] = 0.f; acc[i][j][3] = 0.f;
            }

        auto load_stage = [&](int stg, int k0) {
            #pragma unroll
            for (int i = 0; i < 8; i++) {
                int lin = tid + i * 256;
                int mat = lin >> 9;
                int rem2 = lin & 511;
                int r   = rem2 >> 4;
                int c16 = rem2 & 15;
                const bf16* src = (mat == 0) ? Ah : (mat == 1) ? Al : (mat == 2) ? Bh : Bl;
                int colb = (mat < 2) ? bm : bn;
                src += (long)(k0 + r) * NQKV + colb + c16 * 8;
                uint32_t dst = sb + (uint32_t)stg * TN_STG + mat * TN_MAT
                             + (uint32_t)r * TN_ROW + c16 * 16;
                CPASYNC16(dst, src);
            }
        };
        auto compute_stage = [&](int stg) {
            const uint32_t s0 = sb + (uint32_t)stg * TN_STG;
            #pragma unroll
            for (int kk = 0; kk < 2; kk++) {
                uint32_t a_h[4][4], a_l[4][4], b_h[4][2], b_l[4][2];
                const int akrow = kk * 16 + (L & 7) + ((L >> 4) & 1) * 8;
                const int amcol = ((L >> 3) & 1) * 8;
                #pragma unroll
                for (int mt = 0; mt < 4; mt++) {
                    uint32_t ad = s0 + (uint32_t)akrow * TN_ROW
                                + (uint32_t)(wm * 64 + mt * 16 + amcol) * 2;
                    LDSM4T(a_h[mt][0], a_h[mt][1], a_h[mt][2], a_h[mt][3], ad);
                    LDSM4T(a_l[mt][0], a_l[mt][1], a_l[mt][2], a_l[mt][3], ad + TN_MAT);
                }
                const int bkrow = kk * 16 + (L & 7) + ((L >> 3) & 1) * 8;
                const int bncol = ((L >> 4) & 1) * 8;
                #pragma unroll
                for (int p = 0; p < 2; p++) {
                    uint32_t bd = s0 + 2 * TN_MAT + (uint32_t)bkrow * TN_ROW
                                + (uint32_t)(wn * 32 + p * 16 + bncol) * 2;
                    uint32_t r0, r1, r2, r3;
                    LDSM4T(r0, r1, r2, r3, bd);
                    b_h[2 * p][0] = r0; b_h[2 * p][1] = r1;
                    b_h[2 * p + 1][0] = r2; b_h[2 * p + 1][1] = r3;
                    LDSM4T(r0, r1, r2, r3, bd + TN_MAT);
                    b_l[2 * p][0] = r0; b_l[2 * p][1] = r1;
                    b_l[2 * p + 1][0] = r2; b_l[2 * p + 1][1] = r3;
                }
                MMA_TERMS_4x4(acc, a_h, a_l, b_h, b_l);
            }
        };

        const int iters = CHUNK >> 5;   // 4
        load_stage(0, 0);
        CPCOMMIT();
        for (int it = 0; it < iters; it++) {
            if (it + 1 < iters) {
                load_stage((it + 1) & 1, (it + 1) * 32);
                CPCOMMIT();
                CPWAIT1();
            } else {
                CPWAIT0();
            }
            __syncthreads();
            compute_stage(it & 1);
            __syncthreads();
        }

        #pragma unroll
        for (int mt = 0; mt < 4; mt++)
            #pragma unroll
            for (int nt = 0; nt < 4; nt++) {
                int rr = bm + wm * 64 + mt * 16 + (L >> 2);
                int cc = bn + wn * 32 + nt * 8 + (L & 3) * 2;
                *(float2*)&C[(long)rr * DKV + cc]       = make_float2(acc[mt][nt][0], acc[mt][nt][1]);
                *(float2*)&C[(long)(rr + 8) * DKV + cc] = make_float2(acc[mt][nt][2], acc[mt][nt][3]);
            }
        __syncthreads();
    }
}

// ===========================================================================
// Kernel 3: fused Y_c = P_c V_c + Q_c M_c   (NN x2: A normal, B trans), 2-stage
// ===========================================================================
#define YROW    80
#define Y_AMAT  (128 * YROW)       // 10240
#define Y_BOFF  (2 * Y_AMAT)       // 20480
#define Y_BMAT  (32 * TN_ROW)      // 8704
#define Y_STG   (Y_BOFF + 2 * Y_BMAT)  // 37888
#define Y_SMEM  (2 * Y_STG)        // 75776
#define Y_ITERS 20

__global__ __launch_bounds__(256)
void y_mma()
{
    extern __shared__ char smem[];
    const uint32_t sb = smem_u32(smem);
    const int tid = threadIdx.x;
    const int L   = tid & 31;
    const int w   = tid >> 5;
    const int wm  = w >> 2;
    const int wn  = w & 3;

    const int bn = blockIdx.y * 128;
    const int z  = blockIdx.x;

    const bf16* Ph = g_Ph + (long)z * CHUNK * CHUNK;
    const bf16* Pl = g_Pl + (long)z * CHUNK * CHUNK;
    const bf16* Vh = g_QKVh + 2 * DKV + (long)z * CHUNK * NQKV;
    const bf16* Vl = g_QKVl + 2 * DKV + (long)z * CHUNK * NQKV;
    const bf16* Qh = g_QKVh + (long)z * CHUNK * NQKV;
    const bf16* Ql = g_QKVl + (long)z * CHUNK * NQKV;
    const bf16* Mh = g_Mh + (long)z * DKV * DKV;
    const bf16* Ml = g_Ml + (long)z * DKV * DKV;

    float acc[4][4][4];
    #pragma unroll
    for (int i = 0; i < 4; i++)
        #pragma unroll
        for (int j = 0; j < 4; j++) {
            acc[i][j][0] = 0.f; acc[i][j][1] = 0.f;
            acc[i][j][2] = 0.f; acc[i][j][3] = 0.f;
        }

    auto load_stage = [&](int stg, int it) {
        const int ph1 = (it < 4);
        const int k0  = ph1 ? it * 32 : (it - 4) * 32;
        const bf16* APh = ph1 ? Ph : Qh;
        const bf16* APl = ph1 ? Pl : Ql;
        const int   Alda = ph1 ? CHUNK : NQKV;
        const bf16* BPh = ph1 ? Vh : Mh;
        const bf16* BPl = ph1 ? Vl : Ml;
        const int   Bldb = ph1 ? NQKV : DKV;
        #pragma unroll
        for (int i = 0; i < 4; i++) {
            int lin = tid + i * 256;
            int mat = lin >> 9;
            int rem = lin & 511;
            int r   = rem >> 2;
            int c16 = rem & 3;
            const bf16* src = (mat ? APl : APh) + (long)r * Alda + k0 + c16 * 8;
            uint32_t dst = sb + (uint32_t)stg * Y_STG + mat * Y_AMAT
                         + (uint32_t)r * YROW + c16 * 16;
            CPASYNC16(dst, src);
        }
        #pragma unroll
        for (int i = 0; i < 4; i++) {
            int lin = tid + i * 256;
            int mat = lin >> 9;
            int rem = lin & 511;
            int r   = rem >> 4;
            int c16 = rem & 15;
            const bf16* src = (mat ? BPl : BPh) + (long)(k0 + r) * Bldb + bn + c16 * 8;
            uint32_t dst = sb + (uint32_t)stg * Y_STG + Y_BOFF + mat * Y_BMAT
                         + (uint32_t)r * TN_ROW + c16 * 16;
            CPASYNC16(dst, src);
        }
    };
    auto compute_stage = [&](int stg) {
        const uint32_t s0 = sb + (uint32_t)stg * Y_STG;
        #pragma unroll
        for (int kk = 0; kk < 2; kk++) {
            uint32_t a_h[4][4], a_l[4][4], b_h[4][2], b_l[4][2];
            const int arow  = wm * 64 + (L & 7) + ((L >> 3) & 1) * 8;
            const int acolB = kk * 32 + ((L >> 4) & 1) * 16;
            #pragma unroll
            for (int mt = 0; mt < 4; mt++) {
                uint32_t ad = s0 + (uint32_t)(arow + mt * 16) * YROW + acolB;
                LDSM4(a_h[mt][0], a_h[mt][1], a_h[mt][2], a_h[mt][3], ad);
                LDSM4(a_l[mt][0], a_l[mt][1], a_l[mt][2], a_l[mt][3], ad + Y_AMAT);
            }
            const int bkrow = kk * 16 + (L & 7) + ((L >> 3) & 1) * 8;
            const int bncol = ((L >> 4) & 1) * 8;
            #pragma unroll
            for (int p = 0; p < 2; p++) {
                uint32_t bd = s0 + Y_BOFF + (uint32_t)bkrow * TN_ROW
                            + (uint32_t)(wn * 32 + p * 16 + bncol) * 2;
                uint32_t r0, r1, r2, r3;
                LDSM4T(r0, r1, r2, r3, bd);
                b_h[2 * p][0] = r0; b_h[2 * p][1] = r1;
                b_h[2 * p + 1][0] = r2; b_h[2 * p + 1][1] = r3;
                LDSM4T(r0, r1, r2, r3, bd + Y_BMAT);
                b_l[2 * p][0] = r0; b_l[2 * p][1] = r1;
                b_l[2 * p + 1][0] = r2; b_l[2 * p + 1][1] = r3;
            }
            MMA_TERMS_4x4(acc, a_h, a_l, b_h, b_l);
        }
    };

    load_stage(0, 0);
    CPCOMMIT();
    for (int it = 0; it < Y_ITERS; it++) {
        if (it + 1 < Y_ITERS) {
            load_stage((it + 1) & 1, it + 1);
            CPCOMMIT();
            CPWAIT1();
        } else {
            CPWAIT0();
        }
        __syncthreads();
        compute_stage(it & 1);
        __syncthreads();
    }

    bf16* YH = g_Yh + (long)z * CHUNK * DKV;
    bf16* YL = g_Yl + (long)z * CHUNK * DKV;
    #pragma unroll
    for (int mt = 0; mt < 4; mt++)
        #pragma unroll
        for (int nt = 0; nt < 4; nt++) {
            int rr = wm * 64 + mt * 16 + (L >> 2);
            int cc = bn + wn * 32 + nt * 8 + (L & 3) * 2;
            __nv_bfloat162 h2, l2;
            split_hilo(acc[mt][nt][0], h2.x, l2.x);
            split_hilo(acc[mt][nt][1], h2.y, l2.y);
            *(__nv_bfloat162*)&YH[(long)rr * DKV + cc] = h2;
            *(__nv_bfloat162*)&YL[(long)rr * DKV + cc] = l2;
            split_hilo(acc[mt][nt][2], h2.x, l2.x);
            split_hilo(acc[mt][nt][3], h2.y, l2.y);
            *(__nv_bfloat162*)&YH[(long)(rr + 8) * DKV + cc] = h2;
            *(__nv_bfloat162*)&YL[(long)(rr + 8) * DKV + cc] = l2;
        }
}

// ---------------------------------------------------------------------------
// Exclusive prefix over chunks, MLP version: load all 16, prefix, store.
// ---------------------------------------------------------------------------
__global__ __launch_bounds__(256)
void prefix_kernel()
{
    long idx = (long)blockIdx.x * blockDim.x + threadIdx.x;
    int  b   = (int)(idx / ((long)DKV * DKV));
    long ij  = idx % ((long)DKV * DKV);
    long base = (long)b * NC * DKV * DKV + ij;

    float s[NC];
    #pragma unroll
    for (int c = 0; c < NC; c++)
        s[c] = g_S[base + (long)c * DKV * DKV];

    float acc = 0.0f;
    #pragma unroll
    for (int c = 0; c < NC; c++) {
        bf16 hb, lb;
        split_hilo(acc, hb, lb);
        long off = base + (long)c * DKV * DKV;
        g_Mh[off] = hb;
        g_Ml[off] = lb;
        acc += s[c];
    }
}

// ---------------------------------------------------------------------------
// Input conversions: x (one launch) + all four weights (one launch)
// ---------------------------------------------------------------------------
#define NW  ((long)DKV * DM)         // 524288

__global__ __launch_bounds__(256)
void cvt_hilo(const float* __restrict__ s, bf16* __restrict__ h,
              bf16* __restrict__ l, long n)
{
    long i = (long)blockIdx.x * 256 + threadIdx.x;
    if (i < n) {
        bf16 hb, lb;
        split_hilo(s[i], hb, lb);
        h[i] = hb;
        l[i] = lb;
    }
}

__global__ __launch_bounds__(256)
void cvt_w4(const float* __restrict__ wq, const float* __restrict__ wk,
            const float* __restrict__ wv, const float* __restrict__ wo)
{
    long i = (long)blockIdx.x * 256 + threadIdx.x;   // over 4*NW
    const float* s;
    long j;
    bf16 *h, *l;
    if (i < NW)            { s = wq; j = i;          h = g_Wh;          l = g_Wl; }
    else if (i < 2 * NW)   { s = wk; j = i - NW;     h = g_Wh + NW;     l = g_Wl + NW; }
    else if (i < 3 * NW)   { s = wv; j = i - 2 * NW; h = g_Wh + 2 * NW; l = g_Wl + 2 * NW; }
    else                   { s = wo; j = i - 3 * NW; h = g_Woh;         l = g_Wol; }
    bf16 hb, lb;
    split_hilo(s[j], hb, lb);
    h[j] = hb;
    l[j] = lb;
}

// ---------------------------------------------------------------------------
// Launch
// ---------------------------------------------------------------------------
extern "C" void kernel_launch(void* const* d_in, const int* in_sizes, int n_in,
                              void* d_out, int out_size)
{
    const float* x  = (const float*)d_in[0];
    const float* Wq = (const float*)d_in[1];
    const float* Wk = (const float*)d_in[2];
    const float* Wv = (const float*)d_in[3];
    const float* Wo = (const float*)d_in[4];
    float* out = (float*)d_out;

    bf16 *xh, *xl, *Wh, *Wl, *Woh, *Wol, *QKVh, *QKVl, *Yh, *Yl;
    cudaGetSymbolAddress((void**)&xh, g_xh);
    cudaGetSymbolAddress((void**)&xl, g_xl);
    cudaGetSymbolAddress((void**)&Wh, g_Wh);
    cudaGetSymbolAddress((void**)&Wl, g_Wl);
    cudaGetSymbolAddress((void**)&Woh, g_Woh);
    cudaGetSymbolAddress((void**)&Wol, g_Wol);
    cudaGetSymbolAddress((void**)&QKVh, g_QKVh);
    cudaGetSymbolAddress((void**)&QKVl, g_QKVl);
    cudaGetSymbolAddress((void**)&Yh, g_Yh);
    cudaGetSymbolAddress((void**)&Yl, g_Yl);

    cudaFuncSetAttribute(gemm_mma_nt, cudaFuncAttributeMaxDynamicSharedMemorySize, NT_SMEM);
    cudaFuncSetAttribute(sp_mma,      cudaFuncAttributeMaxDynamicSharedMemorySize, SP_SMEM);
    cudaFuncSetAttribute(y_mma,       cudaFuncAttributeMaxDynamicSharedMemorySize, Y_SMEM);

    // 0) input conversions (2 launches)
    {
        long nx = (long)MTOT * DM;
        cvt_hilo<<<(int)(nx / 256), 256>>>(x, xh, xl, nx);
        cvt_w4<<<(int)(4 * NW / 256), 256>>>(Wq, Wk, Wv, Wo);
    }

    // 1) QKV projection (persistent, 64x12 tiles)
    gemm_mma_nt<<<NSM_SLOTS, 128, NT_SMEM>>>(xh, xl, Wh, Wl,
                                             nullptr, QKVh, QKVl,
                                             DM, DM, DM, NQKV,
                                             1, MTOT / 128, NQKV / 128);

    // 2) fused: P_z (CTAs 0..63) + S tiles (CTAs 64..295)
    sp_mma<<<NSM_SLOTS, 256, SP_SMEM>>>();

    // 3) exclusive prefix -> M hi/lo (MLP-16)
    {
        long n = (long)BB * DKV * DKV;
        prefix_kernel<<<(int)(n / 256), 256>>>();
    }

    // 4) Y_c = P_c V_c + Q_c M_c -> bf16 hi/lo
    {
        dim3 grid(BB * NC, DKV / 128, 1);
        y_mma<<<grid, 256, Y_SMEM>>>();
    }

    // 5) out = Y @ Wo^T (persistent, 64x8 tiles)
    gemm_mma_nt<<<NSM_SLOTS, 128, NT_SMEM>>>(Yh, Yl, Woh, Wol,
                                             out, nullptr, nullptr,
                                             DKV, DKV, DKV, DM,
                                             0, MTOT / 128, DM / 128);
}

// round 17
// speedup vs baseline: 1.0591x; 1.0007x over previous
#include <cuda_runtime.h>
#include <cuda_bf16.h>
#include <cstdint>

// Problem dims
#define BB    4
#define TT    2048
#define DM    1024
#define DKV   512
#define CHUNK 128
#define NC    (TT / CHUNK)   // 16
#define MTOT  (BB * TT)      // 8192
#define NQKV  (3 * DKV)      // 1536

#define NSM_SLOTS 296        // 148 SMs x 2 CTAs (persistent grid)

typedef __nv_bfloat16 bf16;

// ---------------------------------------------------------------------------
// Scratch
// ---------------------------------------------------------------------------
__device__ float g_S[(long)BB * NC * DKV * DKV];      // chunk states (fp32)

__device__ bf16 g_xh[MTOT * DM];
__device__ bf16 g_xl[MTOT * DM];
__device__ bf16 g_Wh[NQKV * DM];     // Wq|Wk|Wv stacked [1536,1024]
__device__ bf16 g_Wl[NQKV * DM];
__device__ bf16 g_Woh[DM * DKV];
__device__ bf16 g_Wol[DM * DKV];
__device__ bf16 g_QKVh[(long)MTOT * NQKV];   // Q|K|V cols, ld=1536
__device__ bf16 g_QKVl[(long)MTOT * NQKV];
__device__ bf16 g_Mh[(long)BB * NC * DKV * DKV];   // exclusive-prefix state
__device__ bf16 g_Ml[(long)BB * NC * DKV * DKV];
__device__ bf16 g_Ph[BB * NC * CHUNK * CHUNK];
__device__ bf16 g_Pl[BB * NC * CHUNK * CHUNK];
__device__ bf16 g_Yh[MTOT * DKV];
__device__ bf16 g_Yl[MTOT * DKV];

// ---------------------------------------------------------------------------
// Helpers
// ---------------------------------------------------------------------------
__device__ __forceinline__ uint32_t smem_u32(const void* p) {
    uint32_t a;
    asm("{ .reg .u64 t; cvta.to.shared.u64 t, %1; cvt.u32.u64 %0, t; }" : "=r"(a) : "l"(p));
    return a;
}

#define CPASYNC16(s, g) \
    asm volatile("cp.async.cg.shared.global [%0], [%1], 16;" :: "r"(s), "l"(g))
#define CPCOMMIT() asm volatile("cp.async.commit_group;" ::: "memory")
#define CPWAIT1()  asm volatile("cp.async.wait_group 1;" ::: "memory")
#define CPWAIT0()  asm volatile("cp.async.wait_group 0;" ::: "memory")

#define LDSM4(r0, r1, r2, r3, a) \
    asm volatile("ldmatrix.sync.aligned.m8n8.x4.shared.b16 {%0,%1,%2,%3}, [%4];" \
                 : "=r"(r0), "=r"(r1), "=r"(r2), "=r"(r3) : "r"(a))
#define LDSM4T(r0, r1, r2, r3, a) \
    asm volatile("ldmatrix.sync.aligned.m8n8.x4.trans.shared.b16 {%0,%1,%2,%3}, [%4];" \
                 : "=r"(r0), "=r"(r1), "=r"(r2), "=r"(r3) : "r"(a))

#define MMA16816(d, a, b) \
    asm volatile("mma.sync.aligned.m16n8k16.row.col.f32.bf16.bf16.f32 " \
                 "{%0,%1,%2,%3},{%4,%5,%6,%7},{%8,%9},{%0,%1,%2,%3};" \
                 : "+f"((d)[0]), "+f"((d)[1]), "+f"((d)[2]), "+f"((d)[3]) \
                 : "r"((a)[0]), "r"((a)[1]), "r"((a)[2]), "r"((a)[3]), \
                   "r"((b)[0]), "r"((b)[1]))

#define MMA_TERMS_4x4(acc, a_h, a_l, b_h, b_l) do {                    \
    _Pragma("unroll")                                                  \
    for (int mt = 0; mt < 4; mt++)                                     \
        _Pragma("unroll")                                              \
        for (int nt = 0; nt < 4; nt++)                                 \
            MMA16816(acc[mt][nt], a_h[mt], b_h[nt]);                   \
    _Pragma("unroll")                                                  \
    for (int mt = 0; mt < 4; mt++)                                     \
        _Pragma("unroll")                                              \
        for (int nt = 0; nt < 4; nt++)                                 \
            MMA16816(acc[mt][nt], a_h[mt], b_l[nt]);                   \
    _Pragma("unroll")                                                  \
    for (int mt = 0; mt < 4; mt++)                                     \
        _Pragma("unroll")                                              \
        for (int nt = 0; nt < 4; nt++)                                 \
            MMA16816(acc[mt][nt], a_l[mt], b_h[nt]);                   \
} while (0)

#define MMA_TERMS_4x8(acc, a_h, a_l, b_h, b_l) do {                    \
    _Pragma("unroll")                                                  \
    for (int mt = 0; mt < 4; mt++)                                     \
        _Pragma("unroll")                                              \
        for (int nt = 0; nt < 8; nt++)                                 \
            MMA16816(acc[mt][nt], a_h[mt], b_h[nt]);                   \
    _Pragma("unroll")                                                  \
    for (int mt = 0; mt < 4; mt++)                                     \
        _Pragma("unroll")                                              \
        for (int nt = 0; nt < 8; nt++)                                 \
            MMA16816(acc[mt][nt], a_h[mt], b_l[nt]);                   \
    _Pragma("unroll")                                                  \
    for (int mt = 0; mt < 4; mt++)                                     \
        _Pragma("unroll")                                              \
        for (int nt = 0; nt < 8; nt++)                                 \
            MMA16816(acc[mt][nt], a_l[mt], b_h[nt]);                   \
} while (0)

__device__ __forceinline__ void split_hilo(float v, bf16& h, bf16& l) {
    h = __float2bfloat16(v);
    l = __float2bfloat16(v - __bfloat162float(h));
}

// ===========================================================================
// Kernel 1: NT GEMM — bf16x3, PERSISTENT. CTA 128x128, 4 warps, 64x64 warp
// tile, swizzled 64B rows, 3 stages, one barrier/iter.  (QKV, Wo)
// ===========================================================================
#define NT_MROW 64
#define NT_MAT  (128 * NT_MROW)    // 8192
#define NT_STG  (4 * NT_MAT)       // 32768
#define NT_NSTG 3
#define NT_SMEM (NT_NSTG * NT_STG) // 98304

__device__ __forceinline__ uint32_t swz64(int row, int c16) {
    return (uint32_t)(row * 64 + ((c16 ^ ((row >> 1) & 3)) << 4));
}

__global__ __launch_bounds__(128, 2)
void gemm_mma_nt(const bf16* __restrict__ Ah_, const bf16* __restrict__ Al_,
                 const bf16* __restrict__ Bh_, const bf16* __restrict__ Bl_,
                 float* Cf, bf16* Ch, bf16* Cl,
                 int K, int lda, int ldb, int ldc,
                 int outmode, int nTm, int nTn)
{
    extern __shared__ char smem[];
    const uint32_t sb = smem_u32(smem);
    const int tid = threadIdx.x;
    const int L   = tid & 31;
    const int w   = tid >> 5;
    const int wm  = w >> 1;
    const int wn  = w & 1;
    const int iters = K >> 5;
    const int total = nTm * nTn;

    for (int t = blockIdx.x; t < total; t += gridDim.x) {
        const int bm  = (t / nTn) * 128;
        const int bn  = (t % nTn) * 128;

        float acc[4][8][4];
        #pragma unroll
        for (int i = 0; i < 4; i++)
            #pragma unroll
            for (int j = 0; j < 8; j++) {
                acc[i][j][0] = 0.f; acc[i][j][1] = 0.f;
                acc[i][j][2] = 0.f; acc[i][j][3] = 0.f;
            }

        auto load_stage = [&](int stg, int k0) {
            uint32_t sbase = sb + (uint32_t)stg * NT_STG;
            const int lrow = tid;
            long ga = (long)(bm + lrow) * lda + k0;
            long gb = (long)(bn + lrow) * ldb + k0;
            #pragma unroll
            for (int c16 = 0; c16 < 4; c16++) {
                uint32_t dsw = sbase + swz64(lrow, c16);
                CPASYNC16(dsw + 0 * NT_MAT, Ah_ + ga + c16 * 8);
                CPASYNC16(dsw + 1 * NT_MAT, Al_ + ga + c16 * 8);
                CPASYNC16(dsw + 2 * NT_MAT, Bh_ + gb + c16 * 8);
                CPASYNC16(dsw + 3 * NT_MAT, Bl_ + gb + c16 * 8);
            }
        };
        auto compute_stage = [&](int stg) {
            const uint32_t s0 = sb + (uint32_t)stg * NT_STG;
            #pragma unroll
            for (int kk = 0; kk < 2; kk++) {
                uint32_t a_h[4][4], a_l[4][4], b_h[8][2], b_l[8][2];
                const int arow = wm * 64 + (L & 7) + ((L >> 3) & 1) * 8;
                const int ac16 = kk * 2 + ((L >> 4) & 1);
                #pragma unroll
                for (int mt = 0; mt < 4; mt++) {
                    uint32_t ad = s0 + swz64(arow + mt * 16, ac16);
                    LDSM4(a_h[mt][0], a_h[mt][1], a_h[mt][2], a_h[mt][3], ad);
                    LDSM4(a_l[mt][0], a_l[mt][1], a_l[mt][2], a_l[mt][3], ad + NT_MAT);
                }
                const int brow = wn * 64 + (L & 7) + ((L >> 4) & 1) * 8;
                const int bc16 = kk * 2 + ((L >> 3) & 1);
                #pragma unroll
                for (int p = 0; p < 4; p++) {
                    uint32_t bd = s0 + 2 * NT_MAT + swz64(brow + p * 16, bc16);
                    uint32_t r0, r1, r2, r3;
                    LDSM4(r0, r1, r2, r3, bd);
                    b_h[2 * p][0] = r0; b_h[2 * p][1] = r1;
                    b_h[2 * p + 1][0] = r2; b_h[2 * p + 1][1] = r3;
                    LDSM4(r0, r1, r2, r3, bd + NT_MAT);
                    b_l[2 * p][0] = r0; b_l[2 * p][1] = r1;
                    b_l[2 * p + 1][0] = r2; b_l[2 * p + 1][1] = r3;
                }
                MMA_TERMS_4x8(acc, a_h, a_l, b_h, b_l);
            }
        };

        load_stage(0, 0);
        CPCOMMIT();
        load_stage(1, 32);
        CPCOMMIT();
        int ld_stg = 2, cp_stg = 0;
        for (int it = 0; it < iters; it++) {
            if (it + 2 < iters) CPWAIT1(); else CPWAIT0();
            __syncthreads();
            if (it + 2 < iters) {
                load_stage(ld_stg, (it + 2) * 32);
                CPCOMMIT();
                if (++ld_stg == NT_NSTG) ld_stg = 0;
            }
            compute_stage(cp_stg);
            if (++cp_stg == NT_NSTG) cp_stg = 0;
        }

        #pragma unroll
        for (int mt = 0; mt < 4; mt++) {
            #pragma unroll
            for (int nt = 0; nt < 8; nt++) {
                int rr = bm + wm * 64 + mt * 16 + (L >> 2);
                int cc = bn + wn * 64 + nt * 8 + (L & 3) * 2;
                float d0 = acc[mt][nt][0], d1 = acc[mt][nt][1];
                float d2 = acc[mt][nt][2], d3 = acc[mt][nt][3];
                if (outmode == 0) {
                    *(float2*)&Cf[(long)rr * ldc + cc]       = make_float2(d0, d1);
                    *(float2*)&Cf[(long)(rr + 8) * ldc + cc] = make_float2(d2, d3);
                } else {
                    __nv_bfloat162 h2, l2;
                    split_hilo(d0, h2.x, l2.x); split_hilo(d1, h2.y, l2.y);
                    *(__nv_bfloat162*)&Ch[(long)rr * ldc + cc] = h2;
                    *(__nv_bfloat162*)&Cl[(long)rr * ldc + cc] = l2;
                    split_hilo(d2, h2.x, l2.x); split_hilo(d3, h2.y, l2.y);
                    *(__nv_bfloat162*)&Ch[(long)(rr + 8) * ldc + cc] = h2;
                    *(__nv_bfloat162*)&Cl[(long)(rr + 8) * ldc + cc] = l2;
                }
            }
        }
        __syncthreads();
    }
}

// ===========================================================================
// Kernel 2: fused S+P persistent kernel (256 threads).
//  - CTAs 0..63:   P_z = strict_tril(Q_z K_z^T), 128x128, K=512 (NT, 80B pitch)
//  - CTAs 64..295: S tiles (z, bm, bn) of S_c = K_c^T V_c (TN, 272B pitch)
// ===========================================================================
#define TN_ROW  272
#define TN_MAT  (32 * TN_ROW)     // 8704
#define TN_STG  (4 * TN_MAT)      // 34816
#define TN_TM   (DKV / 128)       // 4
#define TN_TN   (DKV / 128)       // 4
#define TN_TOTAL (BB * NC * TN_TM * TN_TN)   // 1024

#define P_MROW  80
#define P_MAT   (128 * P_MROW)    // 10240
#define P_STG   (4 * P_MAT)       // 40960
#define SP_SMEM (2 * P_STG)       // 81920 (>= 2*TN_STG)

__global__ __launch_bounds__(256, 2)
void sp_mma()
{
    extern __shared__ char smem[];
    const uint32_t sb = smem_u32(smem);
    const int tid = threadIdx.x;
    const int L   = tid & 31;
    const int w   = tid >> 5;
    const int wm  = w >> 2;       // 0..1
    const int wn  = w & 3;        // 0..3
    const int bid = blockIdx.x;

    if (bid < BB * NC) {
        // ---------------- P path: one z-tile per CTA, NT, K=512 -----------
        const int z = bid;
        const bf16* Ah = g_QKVh + (long)z * CHUNK * NQKV;          // Q
        const bf16* Al = g_QKVl + (long)z * CHUNK * NQKV;
        const bf16* Bh = g_QKVh + DKV + (long)z * CHUNK * NQKV;    // K
        const bf16* Bl = g_QKVl + DKV + (long)z * CHUNK * NQKV;
        bf16* CH = g_Ph + (long)z * CHUNK * CHUNK;
        bf16* CL = g_Pl + (long)z * CHUNK * CHUNK;

        const int lrow = tid & 127;
        const int lc0  = tid >> 7;

        float acc[4][4][4];
        #pragma unroll
        for (int i = 0; i < 4; i++)
            #pragma unroll
            for (int j = 0; j < 4; j++) {
                acc[i][j][0] = 0.f; acc[i][j][1] = 0.f;
                acc[i][j][2] = 0.f; acc[i][j][3] = 0.f;
            }

        auto load_stage = [&](int stg, int k0) {
            uint32_t sdst = sb + (uint32_t)stg * P_STG + (uint32_t)lrow * P_MROW;
            const bf16* aR = Ah + (long)lrow * NQKV + k0;
            const bf16* lR = Al + (long)lrow * NQKV + k0;
            const bf16* bR = Bh + (long)lrow * NQKV + k0;
            const bf16* mR = Bl + (long)lrow * NQKV + k0;
            #pragma unroll
            for (int i2 = 0; i2 < 2; i2++) {
                int c16 = lc0 + i2 * 2;
                CPASYNC16(sdst + 0 * P_MAT + c16 * 16, aR + c16 * 8);
                CPASYNC16(sdst + 1 * P_MAT + c16 * 16, lR + c16 * 8);
                CPASYNC16(sdst + 2 * P_MAT + c16 * 16, bR + c16 * 8);
                CPASYNC16(sdst + 3 * P_MAT + c16 * 16, mR + c16 * 8);
            }
        };
        auto compute_stage = [&](int stg) {
            const uint32_t s0 = sb + (uint32_t)stg * P_STG;
            #pragma unroll
            for (int kk = 0; kk < 2; kk++) {
                uint32_t a_h[4][4], a_l[4][4], b_h[4][2], b_l[4][2];
                const int arow  = wm * 64 + (L & 7) + ((L >> 3) & 1) * 8;
                const int acolB = kk * 32 + ((L >> 4) & 1) * 16;
                #pragma unroll
                for (int mt = 0; mt < 4; mt++) {
                    uint32_t ad = s0 + (uint32_t)(arow + mt * 16) * P_MROW + acolB;
                    LDSM4(a_h[mt][0], a_h[mt][1], a_h[mt][2], a_h[mt][3], ad);
                    LDSM4(a_l[mt][0], a_l[mt][1], a_l[mt][2], a_l[mt][3], ad + P_MAT);
                }
                const int brow  = wn * 32 + (L & 7) + ((L >> 4) & 1) * 8;
                const int bcolB = kk * 32 + ((L >> 3) & 1) * 16;
                #pragma unroll
                for (int p = 0; p < 2; p++) {
                    uint32_t bd = s0 + 2 * P_MAT + (uint32_t)(brow + p * 16) * P_MROW + bcolB;
                    uint32_t r0, r1, r2, r3;
                    LDSM4(r0, r1, r2, r3, bd);
                    b_h[2 * p][0] = r0; b_h[2 * p][1] = r1;
                    b_h[2 * p + 1][0] = r2; b_h[2 * p + 1][1] = r3;
                    LDSM4(r0, r1, r2, r3, bd + P_MAT);
                    b_l[2 * p][0] = r0; b_l[2 * p][1] = r1;
                    b_l[2 * p + 1][0] = r2; b_l[2 * p + 1][1] = r3;
                }
                MMA_TERMS_4x4(acc, a_h, a_l, b_h, b_l);
            }
        };

        const int iters = DKV >> 5;   // 16
        load_stage(0, 0);
        CPCOMMIT();
        for (int it = 0; it < iters; it++) {
            if (it + 1 < iters) {
                load_stage((it + 1) & 1, (it + 1) * 32);
                CPCOMMIT();
                CPWAIT1();
            } else {
                CPWAIT0();
            }
            __syncthreads();
            compute_stage(it & 1);
            __syncthreads();
        }

        #pragma unroll
        for (int mt = 0; mt < 4; mt++)
            #pragma unroll
            for (int nt = 0; nt < 4; nt++) {
                int rr = wm * 64 + mt * 16 + (L >> 2);
                int cc = wn * 32 + nt * 8 + (L & 3) * 2;
                float d0 = acc[mt][nt][0], d1 = acc[mt][nt][1];
                float d2 = acc[mt][nt][2], d3 = acc[mt][nt][3];
                if (cc     >= rr)     d0 = 0.0f;
                if (cc + 1 >= rr)     d1 = 0.0f;
                if (cc     >= rr + 8) d2 = 0.0f;
                if (cc + 1 >= rr + 8) d3 = 0.0f;
                __nv_bfloat162 h2, l2;
                split_hilo(d0, h2.x, l2.x); split_hilo(d1, h2.y, l2.y);
                *(__nv_bfloat162*)&CH[(long)rr * CHUNK + cc] = h2;
                *(__nv_bfloat162*)&CL[(long)rr * CHUNK + cc] = l2;
                split_hilo(d2, h2.x, l2.x); split_hilo(d3, h2.y, l2.y);
                *(__nv_bfloat162*)&CH[(long)(rr + 8) * CHUNK + cc] = h2;
                *(__nv_bfloat162*)&CL[(long)(rr + 8) * CHUNK + cc] = l2;
            }
        return;
    }

    // ---------------- S path: strided tiles over 232 CTAs ------------------
    for (int t = bid - BB * NC; t < TN_TOTAL; t += (NSM_SLOTS - BB * NC)) {
        const int z   = t / (TN_TM * TN_TN);
        const int rem = t % (TN_TM * TN_TN);
        const int bm  = (rem / TN_TN) * 128;
        const int bn  = (rem % TN_TN) * 128;
        const bf16* Ah = g_QKVh + DKV      + (long)z * CHUNK * NQKV;   // K
        const bf16* Al = g_QKVl + DKV      + (long)z * CHUNK * NQKV;
        const bf16* Bh = g_QKVh + 2 * DKV  + (long)z * CHUNK * NQKV;   // V
        const bf16* Bl = g_QKVl + 2 * DKV  + (long)z * CHUNK * NQKV;
        float* C = g_S + (long)z * DKV * DKV;

        float acc[4][4][4];
        #pragma unroll
        for (int i = 0; i < 4; i++)
            #pragma unroll
            for (int j = 0; j < 4; j++) {
                acc[i][j][0] = 0.f; acc[i][j][1] = 0.f;
                acc[i][j][2] = 0.f; acc[i][j][3] = 0.f;
            }

        auto load_stage = [&](int stg, int k0) {
            #pragma unroll
            for (int i = 0; i < 8; i++) {
                int lin = tid + i * 256;
                int mat = lin >> 9;
                int rem2 = lin & 511;
                int r   = rem2 >> 4;
                int c16 = rem2 & 15;
                const bf16* src = (mat == 0) ? Ah : (mat == 1) ? Al : (mat == 2) ? Bh : Bl;
                int colb = (mat < 2) ? bm : bn;
                src += (long)(k0 + r) * NQKV + colb + c16 * 8;
                uint32_t dst = sb + (uint32_t)stg * TN_STG + mat * TN_MAT
                             + (uint32_t)r * TN_ROW + c16 * 16;
                CPASYNC16(dst, src);
            }
        };
        auto compute_stage = [&](int stg) {
            const uint32_t s0 = sb + (uint32_t)stg * TN_STG;
            #pragma unroll
            for (int kk = 0; kk < 2; kk++) {
                uint32_t a_h[4][4], a_l[4][4], b_h[4][2], b_l[4][2];
                const int akrow = kk * 16 + (L & 7) + ((L >> 4) & 1) * 8;
                const int amcol = ((L >> 3) & 1) * 8;
                #pragma unroll
                for (int mt = 0; mt < 4; mt++) {
                    uint32_t ad = s0 + (uint32_t)akrow * TN_ROW
                                + (uint32_t)(wm * 64 + mt * 16 + amcol) * 2;
                    LDSM4T(a_h[mt][0], a_h[mt][1], a_h[mt][2], a_h[mt][3], ad);
                    LDSM4T(a_l[mt][0], a_l[mt][1], a_l[mt][2], a_l[mt][3], ad + TN_MAT);
                }
                const int bkrow = kk * 16 + (L & 7) + ((L >> 3) & 1) * 8;
                const int bncol = ((L >> 4) & 1) * 8;
                #pragma unroll
                for (int p = 0; p < 2; p++) {
                    uint32_t bd = s0 + 2 * TN_MAT + (uint32_t)bkrow * TN_ROW
                                + (uint32_t)(wn * 32 + p * 16 + bncol) * 2;
                    uint32_t r0, r1, r2, r3;
                    LDSM4T(r0, r1, r2, r3, bd);
                    b_h[2 * p][0] = r0; b_h[2 * p][1] = r1;
                    b_h[2 * p + 1][0] = r2; b_h[2 * p + 1][1] = r3;
                    LDSM4T(r0, r1, r2, r3, bd + TN_MAT);
                    b_l[2 * p][0] = r0; b_l[2 * p][1] = r1;
                    b_l[2 * p + 1][0] = r2; b_l[2 * p + 1][1] = r3;
                }
                MMA_TERMS_4x4(acc, a_h, a_l, b_h, b_l);
            }
        };

        const int iters = CHUNK >> 5;   // 4
        load_stage(0, 0);
        CPCOMMIT();
        for (int it = 0; it < iters; it++) {
            if (it + 1 < iters) {
                load_stage((it + 1) & 1, (it + 1) * 32);
                CPCOMMIT();
                CPWAIT1();
            } else {
                CPWAIT0();
            }
            __syncthreads();
            compute_stage(it & 1);
            __syncthreads();
        }

        #pragma unroll
        for (int mt = 0; mt < 4; mt++)
            #pragma unroll
            for (int nt = 0; nt < 4; nt++) {
                int rr = bm + wm * 64 + mt * 16 + (L >> 2);
                int cc = bn + wn * 32 + nt * 8 + (L & 3) * 2;
                *(float2*)&C[(long)rr * DKV + cc]       = make_float2(acc[mt][nt][0], acc[mt][nt][1]);
                *(float2*)&C[(long)(rr + 8) * DKV + cc] = make_float2(acc[mt][nt][2], acc[mt][nt][3]);
            }
        __syncthreads();
    }
}

// ===========================================================================
// Kernel 3: fused Y_c = P_c V_c + Q_c M_c   (NN x2: A normal, B trans), 2-stage
// ===========================================================================
#define YROW    80
#define Y_AMAT  (128 * YROW)       // 10240
#define Y_BOFF  (2 * Y_AMAT)       // 20480
#define Y_BMAT  (32 * TN_ROW)      // 8704
#define Y_STG   (Y_BOFF + 2 * Y_BMAT)  // 37888
#define Y_SMEM  (2 * Y_STG)        // 75776
#define Y_ITERS 20

__global__ __launch_bounds__(256)
void y_mma()
{
    extern __shared__ char smem[];
    const uint32_t sb = smem_u32(smem);
    const int tid = threadIdx.x;
    const int L   = tid & 31;
    const int w   = tid >> 5;
    const int wm  = w >> 2;
    const int wn  = w & 3;

    const int bn = blockIdx.y * 128;
    const int z  = blockIdx.x;

    const bf16* Ph = g_Ph + (long)z * CHUNK * CHUNK;
    const bf16* Pl = g_Pl + (long)z * CHUNK * CHUNK;
    const bf16* Vh = g_QKVh + 2 * DKV + (long)z * CHUNK * NQKV;
    const bf16* Vl = g_QKVl + 2 * DKV + (long)z * CHUNK * NQKV;
    const bf16* Qh = g_QKVh + (long)z * CHUNK * NQKV;
    const bf16* Ql = g_QKVl + (long)z * CHUNK * NQKV;
    const bf16* Mh = g_Mh + (long)z * DKV * DKV;
    const bf16* Ml = g_Ml + (long)z * DKV * DKV;

    float acc[4][4][4];
    #pragma unroll
    for (int i = 0; i < 4; i++)
        #pragma unroll
        for (int j = 0; j < 4; j++) {
            acc[i][j][0] = 0.f; acc[i][j][1] = 0.f;
            acc[i][j][2] = 0.f; acc[i][j][3] = 0.f;
        }

    auto load_stage = [&](int stg, int it) {
        const int ph1 = (it < 4);
        const int k0  = ph1 ? it * 32 : (it - 4) * 32;
        const bf16* APh = ph1 ? Ph : Qh;
        const bf16* APl = ph1 ? Pl : Ql;
        const int   Alda = ph1 ? CHUNK : NQKV;
        const bf16* BPh = ph1 ? Vh : Mh;
        const bf16* BPl = ph1 ? Vl : Ml;
        const int   Bldb = ph1 ? NQKV : DKV;
        #pragma unroll
        for (int i = 0; i < 4; i++) {
            int lin = tid + i * 256;
            int mat = lin >> 9;
            int rem = lin & 511;
            int r   = rem >> 2;
            int c16 = rem & 3;
            const bf16* src = (mat ? APl : APh) + (long)r * Alda + k0 + c16 * 8;
            uint32_t dst = sb + (uint32_t)stg * Y_STG + mat * Y_AMAT
                         + (uint32_t)r * YROW + c16 * 16;
            CPASYNC16(dst, src);
        }
        #pragma unroll
        for (int i = 0; i < 4; i++) {
            int lin = tid + i * 256;
            int mat = lin >> 9;
            int rem = lin & 511;
            int r   = rem >> 4;
            int c16 = rem & 15;
            const bf16* src = (mat ? BPl : BPh) + (long)(k0 + r) * Bldb + bn + c16 * 8;
            uint32_t dst = sb + (uint32_t)stg * Y_STG + Y_BOFF + mat * Y_BMAT
                         + (uint32_t)r * TN_ROW + c16 * 16;
            CPASYNC16(dst, src);
        }
    };
    auto compute_stage = [&](int stg) {
        const uint32_t s0 = sb + (uint32_t)stg * Y_STG;
        #pragma unroll
        for (int kk = 0; kk < 2; kk++) {
            uint32_t a_h[4][4], a_l[4][4], b_h[4][2], b_l[4][2];
            const int arow  = wm * 64 + (L & 7) + ((L >> 3) & 1) * 8;
            const int acolB = kk * 32 + ((L >> 4) & 1) * 16;
            #pragma unroll
            for (int mt = 0; mt < 4; mt++) {
                uint32_t ad = s0 + (uint32_t)(arow + mt * 16) * YROW + acolB;
                LDSM4(a_h[mt][0], a_h[mt][1], a_h[mt][2], a_h[mt][3], ad);
                LDSM4(a_l[mt][0], a_l[mt][1], a_l[mt][2], a_l[mt][3], ad + Y_AMAT);
            }
            const int bkrow = kk * 16 + (L & 7) + ((L >> 3) & 1) * 8;
            const int bncol = ((L >> 4) & 1) * 8;
            #pragma unroll
            for (int p = 0; p < 2; p++) {
                uint32_t bd = s0 + Y_BOFF + (uint32_t)bkrow * TN_ROW
                            + (uint32_t)(wn * 32 + p * 16 + bncol) * 2;
                uint32_t r0, r1, r2, r3;
                LDSM4T(r0, r1, r2, r3, bd);
                b_h[2 * p][0] = r0; b_h[2 * p][1] = r1;
                b_h[2 * p + 1][0] = r2; b_h[2 * p + 1][1] = r3;
                LDSM4T(r0, r1, r2, r3, bd + Y_BMAT);
                b_l[2 * p][0] = r0; b_l[2 * p][1] = r1;
                b_l[2 * p + 1][0] = r2; b_l[2 * p + 1][1] = r3;
            }
            MMA_TERMS_4x4(acc, a_h, a_l, b_h, b_l);
        }
    };

    load_stage(0, 0);
    CPCOMMIT();
    for (int it = 0; it < Y_ITERS; it++) {
        if (it + 1 < Y_ITERS) {
            load_stage((it + 1) & 1, it + 1);
            CPCOMMIT();
            CPWAIT1();
        } else {
            CPWAIT0();
        }
        __syncthreads();
        compute_stage(it & 1);
        __syncthreads();
    }

    bf16* YH = g_Yh + (long)z * CHUNK * DKV;
    bf16* YL = g_Yl + (long)z * CHUNK * DKV;
    #pragma unroll
    for (int mt = 0; mt < 4; mt++)
        #pragma unroll
        for (int nt = 0; nt < 4; nt++) {
            int rr = wm * 64 + mt * 16 + (L >> 2);
            int cc = bn + wn * 32 + nt * 8 + (L & 3) * 2;
            __nv_bfloat162 h2, l2;
            split_hilo(acc[mt][nt][0], h2.x, l2.x);
            split_hilo(acc[mt][nt][1], h2.y, l2.y);
            *(__nv_bfloat162*)&YH[(long)rr * DKV + cc] = h2;
            *(__nv_bfloat162*)&YL[(long)rr * DKV + cc] = l2;
            split_hilo(acc[mt][nt][2], h2.x, l2.x);
            split_hilo(acc[mt][nt][3], h2.y, l2.y);
            *(__nv_bfloat162*)&YH[(long)(rr + 8) * DKV + cc] = h2;
            *(__nv_bfloat162*)&YL[(long)(rr + 8) * DKV + cc] = l2;
        }
}

// ---------------------------------------------------------------------------
// Exclusive prefix over chunks, MLP version: load all 16, prefix, store.
// ---------------------------------------------------------------------------
__global__ __launch_bounds__(256)
void prefix_kernel()
{
    long idx = (long)blockIdx.x * blockDim.x + threadIdx.x;
    int  b   = (int)(idx / ((long)DKV * DKV));
    long ij  = idx % ((long)DKV * DKV);
    long base = (long)b * NC * DKV * DKV + ij;

    float s[NC];
    #pragma unroll
    for (int c = 0; c < NC; c++)
        s[c] = g_S[base + (long)c * DKV * DKV];

    float acc = 0.0f;
    #pragma unroll
    for (int c = 0; c < NC; c++) {
        bf16 hb, lb;
        split_hilo(acc, hb, lb);
        long off = base + (long)c * DKV * DKV;
        g_Mh[off] = hb;
        g_Ml[off] = lb;
        acc += s[c];
    }
}

// ---------------------------------------------------------------------------
// Input conversions: x (one launch) + all four weights (one launch)
// ---------------------------------------------------------------------------
#define NW  ((long)DKV * DM)         // 524288

__global__ __launch_bounds__(256)
void cvt_hilo(const float* __restrict__ s, bf16* __restrict__ h,
              bf16* __restrict__ l, long n)
{
    long i = (long)blockIdx.x * 256 + threadIdx.x;
    if (i < n) {
        bf16 hb, lb;
        split_hilo(s[i], hb, lb);
        h[i] = hb;
        l[i] = lb;
    }
}

__global__ __launch_bounds__(256)
void cvt_w4(const float* __restrict__ wq, const float* __restrict__ wk,
            const float* __restrict__ wv, const float* __restrict__ wo)
{
    long i = (long)blockIdx.x * 256 + threadIdx.x;   // over 4*NW
    const float* s;
    long j;
    bf16 *h, *l;
    if (i < NW)            { s = wq; j = i;          h = g_Wh;          l = g_Wl; }
    else if (i < 2 * NW)   { s = wk; j = i - NW;     h = g_Wh + NW;     l = g_Wl + NW; }
    else if (i < 3 * NW)   { s = wv; j = i - 2 * NW; h = g_Wh + 2 * NW; l = g_Wl + 2 * NW; }
    else                   { s = wo; j = i - 3 * NW; h = g_Woh;         l = g_Wol; }
    bf16 hb, lb;
    split_hilo(s[j], hb, lb);
    h[j] = hb;
    l[j] = lb;
}

// ---------------------------------------------------------------------------
// Launch
// ---------------------------------------------------------------------------
extern "C" void kernel_launch(void* const* d_in, const int* in_sizes, int n_in,
                              void* d_out, int out_size)
{
    const float* x  = (const float*)d_in[0];
    const float* Wq = (const float*)d_in[1];
    const float* Wk = (const float*)d_in[2];
    const float* Wv = (const float*)d_in[3];
    const float* Wo = (const float*)d_in[4];
    float* out = (float*)d_out;

    bf16 *xh, *xl, *Wh, *Wl, *Woh, *Wol, *QKVh, *QKVl, *Yh, *Yl;
    cudaGetSymbolAddress((void**)&xh, g_xh);
    cudaGetSymbolAddress((void**)&xl, g_xl);
    cudaGetSymbolAddress((void**)&Wh, g_Wh);
    cudaGetSymbolAddress((void**)&Wl, g_Wl);
    cudaGetSymbolAddress((void**)&Woh, g_Woh);
    cudaGetSymbolAddress((void**)&Wol, g_Wol);
    cudaGetSymbolAddress((void**)&QKVh, g_QKVh);
    cudaGetSymbolAddress((void**)&QKVl, g_QKVl);
    cudaGetSymbolAddress((void**)&Yh, g_Yh);
    cudaGetSymbolAddress((void**)&Yl, g_Yl);

    cudaFuncSetAttribute(gemm_mma_nt, cudaFuncAttributeMaxDynamicSharedMemorySize, NT_SMEM);
    cudaFuncSetAttribute(sp_mma,      cudaFuncAttributeMaxDynamicSharedMemorySize, SP_SMEM);
    cudaFuncSetAttribute(y_mma,       cudaFuncAttributeMaxDynamicSharedMemorySize, Y_SMEM);

    // 0) input conversions (2 launches)
    {
        long nx = (long)MTOT * DM;
        cvt_hilo<<<(int)(nx / 256), 256>>>(x, xh, xl, nx);
        cvt_w4<<<(int)(4 * NW / 256), 256>>>(Wq, Wk, Wv, Wo);
    }

    // 1) QKV projection (persistent, 64x12 tiles)
    gemm_mma_nt<<<NSM_SLOTS, 128, NT_SMEM>>>(xh, xl, Wh, Wl,
                                             nullptr, QKVh, QKVl,
                                             DM, DM, DM, NQKV,
                                             1, MTOT / 128, NQKV / 128);

    // 2) fused: P_z (CTAs 0..63) + S tiles (CTAs 64..295)
    sp_mma<<<NSM_SLOTS, 256, SP_SMEM>>>();

    // 3) exclusive prefix -> M hi/lo (MLP-16)
    {
        long n = (long)BB * DKV * DKV;
        prefix_kernel<<<(int)(n / 256), 256>>>();
    }

    // 4) Y_c = P_c V_c + Q_c M_c -> bf16 hi/lo
    {
        dim3 grid(BB * NC, DKV / 128, 1);
        y_mma<<<grid, 256, Y_SMEM>>>();
    }

    // 5) out = Y @ Wo^T (persistent, 64x8 tiles)
    gemm_mma_nt<<<NSM_SLOTS, 128, NT_SMEM>>>(Yh, Yl, Woh, Wol,
                                             out, nullptr, nullptr,
                                             DKV, DKV, DKV, DM,
                                             0, MTOT / 128, DM / 128);
}